// round 7
// baseline (speedup 1.0000x reference)
#include <cuda_runtime.h>
#include <cstdint>

// ---------------------------------------------------------------------------
// Problem constants
// ---------------------------------------------------------------------------
#define NTOK   256
#define DIM    4096
#define HIDDEN 14336
#define KVDIM  1024
#define NHEAD  32
#define HDIM   128
#define TSTEPS 10

// ---------------------------------------------------------------------------
// Scratch (device globals)
// ---------------------------------------------------------------------------
__device__ float    g_xs [2 * NTOK * DIM];        // stacked [relu(xn); relu(-xn)]
__device__ float    g_hs [2 * NTOK * DIM];
__device__ unsigned g_qm [2 * NTOK * DIM];        // spike masks, rows 0..255 = pos
__device__ unsigned g_km [2 * NTOK * KVDIM];
__device__ unsigned g_vm [2 * NTOK * KVDIM];
__device__ float    g_xat[TSTEPS * NTOK * DIM];   // per-t xa planes (exact ints*0.5)
__device__ float    g_yt [TSTEPS * NTOK * DIM];   // per-t wo GEMM outputs
__device__ float    g_h  [NTOK * DIM];
__device__ float    g_c3 [2 * NTOK * HIDDEN];     // raw spike counts 0..10
__device__ float    g_c1 [NTOK * HIDDEN];

// ---------------------------------------------------------------------------
// RMSNorm + stacked relu branches — XLA:GPU row-reduction emulation.
// (R5==R6 bitwise proved the norm tree order is NOT the error source; keep.)
// ---------------------------------------------------------------------------
__global__ __launch_bounds__(1024)
void rmsnorm_relu_kernel(const float* __restrict__ x,
                         const float* __restrict__ w,
                         float* __restrict__ out)
{
    const int n = blockIdx.x;
    const int t = threadIdx.x;             // 0..1023
    const float* xr = x + (size_t)n * DIM;

    float acc = 0.f;
    #pragma unroll
    for (int i = 0; i < 2; i++) {
        float2 v = *(const float2*)(xr + 2 * t + i * 2048);
        acc += v.x * v.x;
        acc += v.y * v.y;
    }

    #pragma unroll
    for (int o = 16; o > 0; o >>= 1)
        acc += __shfl_down_sync(0xffffffffu, acc, o);

    __shared__ float sw[32];
    __shared__ float sres;
    const int lane = t & 31, wid = t >> 5;
    if (lane == 0) sw[wid] = acc;
    __syncthreads();
    if (wid == 0) {
        float v = sw[lane];
        #pragma unroll
        for (int o = 16; o > 0; o >>= 1)
            v += __shfl_down_sync(0xffffffffu, v, o);
        if (lane == 0) sres = v;
    }
    __syncthreads();

    const float rs = rsqrtf(sres * (1.0f / 4096.0f) + 1e-5f);
    #pragma unroll
    for (int i = 0; i < 4; i++) {
        const int c = t + i * 1024;
        float v = xr[c] * rs * w[c];
        out[(size_t)n * DIM + c]          = fmaxf(v, 0.f);
        out[(size_t)(n + NTOK) * DIM + c] = fmaxf(-v, 0.f);
    }
}

// ---------------------------------------------------------------------------
// GEMM (NT): C = A[M,K] * B[N,K]^T.
//   MODE 0: QKV spike masks. SPLIT-K=4 EMULATION: fp32 sequential within each
//           1024-wide k-chunk, chunks folded ascending (cublas splitK order).
//   MODE 1: FFN spike counts (sequential fp32 — large-N kernels don't split).
//   MODE 2: per-t wo GEMM, plain f32 store, sequential.
//   MODE 3: w2, A = gate on the fly, sequential. Epilogue out = h + y.
// Tile: 128x64, BK=8, per-thread 8x4, 256 threads.
// ---------------------------------------------------------------------------
#define BM 128
#define BN 64
#define BK 8
#define TM 8
#define TN 4
#define SPLITK_CHUNK 1024

template<int MODE>
__global__ __launch_bounds__(256)
void gemm_kernel(const float* __restrict__ A,
                 const float* __restrict__ A2,
                 const float* __restrict__ A3,
                 const float* __restrict__ B0,
                 const float* __restrict__ B1,
                 const float* __restrict__ B2,
                 void* __restrict__ C0, void* __restrict__ C1, void* __restrict__ C2,
                 const float* __restrict__ addv, int K)
{
    constexpr bool SPLITK = (MODE == 0);

    __shared__ float As[BK][BM];
    __shared__ float Bs[BK][BN];

    const int bx = blockIdx.x, by = blockIdx.y;
    const float* B; void* C; int N, bxl, row0;
    if (MODE == 0) {
        row0 = by * BM;
        if (bx < 64)      { B = B0; C = C0; N = DIM;   bxl = bx; }
        else if (bx < 80) { B = B1; C = C1; N = KVDIM; bxl = bx - 64; }
        else              { B = B2; C = C2; N = KVDIM; bxl = bx - 80; }
    } else if (MODE == 1) {
        N = HIDDEN; bxl = bx;
        if (by < 4) { B = B0; C = C0; row0 = by * BM; }
        else        { B = B1; C = C1; row0 = (by - 4) * BM; }
    } else {
        N = DIM; bxl = bx; row0 = by * BM; B = B0; C = C0;
    }

    const int tid = threadIdx.x;
    const int tx = tid & 15;
    const int ty = tid >> 4;

    const int lrow  = tid >> 1;
    const int lcol4 = (tid & 1) * 4;
    const int lrowB = tid >> 1;

    const size_t aoff0 = (size_t)(row0 + lrow) * K + lcol4;
    const float* Aptr  = A  + aoff0;
    const float* A2ptr = (MODE == 3) ? (A2 + aoff0) : nullptr;
    const float* A3ptr = (MODE == 3) ? (A3 + aoff0) : nullptr;
    const float* Bptr  = B + (size_t)(bxl * BN + lrowB) * K + lcol4;

    float acc[TM][TN];           // current chunk accumulator (or the only one)
    float tot[TM][TN];           // split-K running total (MODE 0 only)
    #pragma unroll
    for (int i = 0; i < TM; i++)
        #pragma unroll
        for (int j = 0; j < TN; j++) { acc[i][j] = 0.f; tot[i][j] = 0.f; }

    for (int k0 = 0; k0 < K; k0 += BK) {
        float4 av;
        if (MODE == 3) {
            float4 c1v = *(const float4*)Aptr;
            float4 pv  = *(const float4*)A2ptr;
            float4 nv  = *(const float4*)A3ptr;
            av.x = (c1v.x / 10.0f) * ((pv.x - nv.x) / 10.0f);
            av.y = (c1v.y / 10.0f) * ((pv.y - nv.y) / 10.0f);
            av.z = (c1v.z / 10.0f) * ((pv.z - nv.z) / 10.0f);
            av.w = (c1v.w / 10.0f) * ((pv.w - nv.w) / 10.0f);
            A2ptr += BK; A3ptr += BK;
        } else {
            av = *(const float4*)Aptr;
        }
        Aptr += BK;

        float4 bv = make_float4(0.f, 0.f, 0.f, 0.f);
        if (tid < 128) { bv = *(const float4*)Bptr; }
        Bptr += BK;

        As[lcol4 + 0][lrow] = av.x; As[lcol4 + 1][lrow] = av.y;
        As[lcol4 + 2][lrow] = av.z; As[lcol4 + 3][lrow] = av.w;
        if (tid < 128) {
            Bs[lcol4 + 0][lrowB] = bv.x; Bs[lcol4 + 1][lrowB] = bv.y;
            Bs[lcol4 + 2][lrowB] = bv.z; Bs[lcol4 + 3][lrowB] = bv.w;
        }
        __syncthreads();

        #pragma unroll
        for (int kk = 0; kk < BK; kk++) {
            float a[TM], b[TN];
            float4 a0 = *(const float4*)&As[kk][ty * TM];
            float4 a1 = *(const float4*)&As[kk][ty * TM + 4];
            float4 b0 = *(const float4*)&Bs[kk][tx * TN];
            a[0]=a0.x; a[1]=a0.y; a[2]=a0.z; a[3]=a0.w;
            a[4]=a1.x; a[5]=a1.y; a[6]=a1.z; a[7]=a1.w;
            b[0]=b0.x; b[1]=b0.y; b[2]=b0.z; b[3]=b0.w;
            #pragma unroll
            for (int i = 0; i < TM; i++)
                #pragma unroll
                for (int j = 0; j < TN; j++)
                    acc[i][j] = fmaf(a[i], b[j], acc[i][j]);
        }
        __syncthreads();

        if (SPLITK) {
            // fold chunk partial into running total at each 1024-k boundary,
            // ascending chunk order: (((q0+q1)+q2)+q3)
            if (((k0 + BK) & (SPLITK_CHUNK - 1)) == 0) {
                #pragma unroll
                for (int i = 0; i < TM; i++)
                    #pragma unroll
                    for (int j = 0; j < TN; j++) {
                        tot[i][j] += acc[i][j];
                        acc[i][j] = 0.f;
                    }
            }
        }
    }

    #pragma unroll
    for (int i = 0; i < TM; i++) {
        const int r = row0 + ty * TM + i;
        #pragma unroll
        for (int j = 0; j < TN; j++) {
            const int col = bxl * BN + tx * TN + j;
            const size_t idx = (size_t)r * N + col;
            float y = SPLITK ? tot[i][j] : acc[i][j];
            if (MODE == 0) {
                unsigned m = 0; float vm = 0.f;
                #pragma unroll
                for (int t = 0; t < TSTEPS; t++) {
                    vm += y;
                    if (vm - 1.0f >= 0.f) { m |= (1u << t); vm = 0.f; }
                }
                ((unsigned*)C)[idx] = m;
            } else if (MODE == 1) {
                int cnt = 0; float vm = 0.f;
                #pragma unroll
                for (int t = 0; t < TSTEPS; t++) {
                    vm += y;
                    if (vm - 1.0f >= 0.f) { cnt++; vm = 0.f; }
                }
                ((float*)C)[idx] = (float)cnt;
            } else if (MODE == 2) {
                ((float*)C)[idx] = y;
            } else {
                ((float*)C)[idx] = addv[idx] + y;
            }
        }
    }
}

// ---------------------------------------------------------------------------
// Spike attention, exact integer math, storing PER-TIMESTEP planes:
// xat[t, n, d*32+i] = 0.5 * sum_j S_t[i,j] * v_t[j,d]   (exact in fp32)
// ---------------------------------------------------------------------------
__global__ void attn_kernel(const unsigned* __restrict__ qm,
                            const unsigned* __restrict__ km,
                            const unsigned* __restrict__ vm,
                            float* __restrict__ xat)
{
    __shared__ unsigned sq[128 * 33];
    __shared__ unsigned sk[128 * 9];
    __shared__ unsigned sv[8 * 128];
    __shared__ int      S[NHEAD * 8];

    const int n   = blockIdx.x;
    const int tid = threadIdx.x;

    for (int idx = tid; idx < NHEAD * HDIM; idx += 128) {
        const int i = idx >> 7, d = idx & 127;
        sq[d * 33 + i] = qm[(size_t)n * DIM + idx] | (qm[(size_t)(n + NTOK) * DIM + idx] << 16);
    }
    for (int idx = tid; idx < 8 * HDIM; idx += 128) {
        const int j = idx >> 7, d = idx & 127;
        sk[d * 9 + j] = km[(size_t)n * KVDIM + idx] | (km[(size_t)(n + NTOK) * KVDIM + idx] << 16);
        sv[idx]       = vm[(size_t)n * KVDIM + idx] | (vm[(size_t)(n + NTOK) * KVDIM + idx] << 16);
    }
    __syncthreads();

    for (int t = 0; t < TSTEPS; t++) {
        #pragma unroll
        for (int e0 = 0; e0 < 2; e0++) {
            const int e = tid + e0 * 128;
            const int i = e >> 3, j = e & 7;
            int s = 0;
            for (int d2 = 0; d2 < HDIM; d2++) {
                const unsigned q = sq[d2 * 33 + i];
                const unsigned k = sk[d2 * 9 + j];
                const int qv = (int)((q >> t) & 1u) - (int)((q >> (t + 16)) & 1u);
                const int kv = (int)((k >> t) & 1u) - (int)((k >> (t + 16)) & 1u);
                s += qv * kv;
            }
            S[e] = s;
        }
        __syncthreads();

        {
            const int d2 = tid;
            int vv[8];
            #pragma unroll
            for (int j = 0; j < 8; j++) {
                const unsigned v = sv[j * 128 + d2];
                vv[j] = (int)((v >> t) & 1u) - (int)((v >> (t + 16)) & 1u);
            }
            float* orow = xat + ((size_t)t * NTOK + n) * DIM + (size_t)d2 * NHEAD;
            #pragma unroll
            for (int i = 0; i < NHEAD; i++) {
                int s = 0;
                #pragma unroll
                for (int j = 0; j < 8; j++) s += S[i * 8 + j] * vv[j];
                orow[i] = (float)s * 0.5f;
            }
        }
        __syncthreads();
    }
}

// ---------------------------------------------------------------------------
// h = x + mean_t(y_t): ascending-t sequential fp32 sum, then /10.0f
// ---------------------------------------------------------------------------
__global__ void wo_mean_kernel(const float* __restrict__ yt,
                               const float* __restrict__ x,
                               float* __restrict__ h)
{
    const int idx = blockIdx.x * blockDim.x + threadIdx.x;
    if (idx >= NTOK * DIM) return;
    float s = 0.f;
    #pragma unroll
    for (int t = 0; t < TSTEPS; t++)
        s += yt[(size_t)t * NTOK * DIM + idx];
    h[idx] = x[idx] + s / 10.0f;
}

// ---------------------------------------------------------------------------
// Launch
// ---------------------------------------------------------------------------
extern "C" void kernel_launch(void* const* d_in, const int* in_sizes, int n_in,
                              void* d_out, int out_size)
{
    const float* x           = (const float*)d_in[0];
    const float* attn_norm_w = (const float*)d_in[2];
    const float* ffn_norm_w  = (const float*)d_in[3];
    const float* wq          = (const float*)d_in[4];
    const float* wk          = (const float*)d_in[5];
    const float* wv          = (const float*)d_in[6];
    const float* wo          = (const float*)d_in[7];
    const float* w1          = (const float*)d_in[8];
    const float* w2          = (const float*)d_in[9];
    const float* w3          = (const float*)d_in[10];
    float* out = (float*)d_out;

    float *xs, *hs, *xat, *yt, *h, *c3, *c1;
    unsigned *qm, *km, *vm;
    cudaGetSymbolAddress((void**)&xs,  g_xs);
    cudaGetSymbolAddress((void**)&hs,  g_hs);
    cudaGetSymbolAddress((void**)&qm,  g_qm);
    cudaGetSymbolAddress((void**)&km,  g_km);
    cudaGetSymbolAddress((void**)&vm,  g_vm);
    cudaGetSymbolAddress((void**)&xat, g_xat);
    cudaGetSymbolAddress((void**)&yt,  g_yt);
    cudaGetSymbolAddress((void**)&h,   g_h);
    cudaGetSymbolAddress((void**)&c3,  g_c3);
    cudaGetSymbolAddress((void**)&c1,  g_c1);

    // 1) attn rmsnorm + stacked relu
    rmsnorm_relu_kernel<<<NTOK, 1024>>>(x, attn_norm_w, xs);

    // 2) fused QKV spike-mask projections (M=512), split-K=4 emulation
    gemm_kernel<0><<<dim3(96, 4), 256>>>(xs, nullptr, nullptr,
                                         wq, wk, wv, qm, km, vm, nullptr, DIM);

    // 3) exact spike attention -> per-timestep planes
    attn_kernel<<<NTOK, 128>>>(qm, km, vm, xat);

    // 4) per-t wo GEMM: yt[t,n,:] = xa_t @ wo^T   (M = 2560)
    gemm_kernel<2><<<dim3(64, 20), 256>>>(xat, nullptr, nullptr,
                                          wo, nullptr, nullptr, yt, nullptr, nullptr,
                                          nullptr, DIM);

    // 5) h = x + mean_t(y_t)
    wo_mean_kernel<<<(NTOK * DIM + 255) / 256, 256>>>(yt, x, h);

    // 6) ffn rmsnorm + stacked relu
    rmsnorm_relu_kernel<<<NTOK, 1024>>>(h, ffn_norm_w, hs);

    // 7) fused FFN spike-count projections: w3 (M=512) + w1 (M=256)
    gemm_kernel<1><<<dim3(224, 6), 256>>>(hs, nullptr, nullptr,
                                          w3, w1, nullptr, c3, c1, nullptr, nullptr, DIM);

    // 8) out = h + gate(c1,c3) @ w2^T
    gemm_kernel<3><<<dim3(64, 2), 256>>>(c1, c3, c3 + (size_t)NTOK * HIDDEN,
                                         w2, nullptr, nullptr, out, nullptr, nullptr, h, HIDDEN);
}

// round 8
// speedup vs baseline: 1.0079x; 1.0079x over previous
#include <cuda_runtime.h>
#include <cstdint>

// ---------------------------------------------------------------------------
// Problem constants
// ---------------------------------------------------------------------------
#define NTOK   256
#define DIM    4096
#define HIDDEN 14336
#define KVDIM  1024
#define NHEAD  32
#define HDIM   128
#define TSTEPS 10

// ---------------------------------------------------------------------------
// Scratch (device globals)
// ---------------------------------------------------------------------------
__device__ float    g_xs [2 * NTOK * DIM];        // stacked [relu(xn); relu(-xn)]
__device__ float    g_hs [2 * NTOK * DIM];
__device__ unsigned g_qm [2 * NTOK * DIM];        // spike masks, rows 0..255 = pos
__device__ unsigned g_km [2 * NTOK * KVDIM];
__device__ unsigned g_vm [2 * NTOK * KVDIM];
__device__ float    g_xat[TSTEPS * NTOK * DIM];   // per-t xa planes (exact ints*0.5)
__device__ float    g_yt [TSTEPS * NTOK * DIM];   // per-t wo GEMM outputs
__device__ float    g_h  [NTOK * DIM];
__device__ float    g_c3 [2 * NTOK * HIDDEN];     // raw spike counts 0..10
__device__ float    g_c1 [NTOK * HIDDEN];

// ---------------------------------------------------------------------------
// RMSNorm + stacked relu branches (bit-frozen since R7)
// ---------------------------------------------------------------------------
__global__ __launch_bounds__(1024)
void rmsnorm_relu_kernel(const float* __restrict__ x,
                         const float* __restrict__ w,
                         float* __restrict__ out)
{
    const int n = blockIdx.x;
    const int t = threadIdx.x;
    const float* xr = x + (size_t)n * DIM;

    float acc = 0.f;
    #pragma unroll
    for (int i = 0; i < 2; i++) {
        float2 v = *(const float2*)(xr + 2 * t + i * 2048);
        acc += v.x * v.x;
        acc += v.y * v.y;
    }
    #pragma unroll
    for (int o = 16; o > 0; o >>= 1)
        acc += __shfl_down_sync(0xffffffffu, acc, o);

    __shared__ float sw[32];
    __shared__ float sres;
    const int lane = t & 31, wid = t >> 5;
    if (lane == 0) sw[wid] = acc;
    __syncthreads();
    if (wid == 0) {
        float v = sw[lane];
        #pragma unroll
        for (int o = 16; o > 0; o >>= 1)
            v += __shfl_down_sync(0xffffffffu, v, o);
        if (lane == 0) sres = v;
    }
    __syncthreads();

    const float rs = rsqrtf(sres * (1.0f / 4096.0f) + 1e-5f);
    #pragma unroll
    for (int i = 0; i < 4; i++) {
        const int c = t + i * 1024;
        float v = xr[c] * rs * w[c];
        out[(size_t)n * DIM + c]          = fmaxf(v, 0.f);
        out[(size_t)(n + NTOK) * DIM + c] = fmaxf(-v, 0.f);
    }
}

// ---------------------------------------------------------------------------
// QKV GEMM: split-K=4 emulation (bit-frozen since R7 — DO NOT TOUCH numerics)
// Tile 128x64, BK=8, 8x4/thread, 256 threads.
// ---------------------------------------------------------------------------
#define BM 128
#define BN 64
#define BK 8
#define TM 8
#define TN 4
#define SPLITK_CHUNK 1024

__global__ __launch_bounds__(256)
void gemm_qkv_kernel(const float* __restrict__ A,
                     const float* __restrict__ B0,
                     const float* __restrict__ B1,
                     const float* __restrict__ B2,
                     unsigned* __restrict__ C0, unsigned* __restrict__ C1,
                     unsigned* __restrict__ C2, int K)
{
    __shared__ float As[BK][BM];
    __shared__ float Bs[BK][BN];

    const int bx = blockIdx.x, by = blockIdx.y;
    const float* B; unsigned* C; int N, bxl;
    const int row0 = by * BM;
    if (bx < 64)      { B = B0; C = C0; N = DIM;   bxl = bx; }
    else if (bx < 80) { B = B1; C = C1; N = KVDIM; bxl = bx - 64; }
    else              { B = B2; C = C2; N = KVDIM; bxl = bx - 80; }

    const int tid = threadIdx.x;
    const int tx = tid & 15;
    const int ty = tid >> 4;
    const int lrow  = tid >> 1;
    const int lcol4 = (tid & 1) * 4;

    const float* Aptr = A + (size_t)(row0 + lrow) * K + lcol4;
    const float* Bptr = B + (size_t)(bxl * BN + lrow) * K + lcol4;

    float acc[TM][TN], tot[TM][TN];
    #pragma unroll
    for (int i = 0; i < TM; i++)
        #pragma unroll
        for (int j = 0; j < TN; j++) { acc[i][j] = 0.f; tot[i][j] = 0.f; }

    for (int k0 = 0; k0 < K; k0 += BK) {
        float4 av = *(const float4*)Aptr; Aptr += BK;
        float4 bv = make_float4(0.f, 0.f, 0.f, 0.f);
        if (tid < 128) { bv = *(const float4*)Bptr; }
        Bptr += BK;

        As[lcol4 + 0][lrow] = av.x; As[lcol4 + 1][lrow] = av.y;
        As[lcol4 + 2][lrow] = av.z; As[lcol4 + 3][lrow] = av.w;
        if (tid < 128) {
            Bs[lcol4 + 0][lrow] = bv.x; Bs[lcol4 + 1][lrow] = bv.y;
            Bs[lcol4 + 2][lrow] = bv.z; Bs[lcol4 + 3][lrow] = bv.w;
        }
        __syncthreads();

        #pragma unroll
        for (int kk = 0; kk < BK; kk++) {
            float a[TM], b[TN];
            float4 a0 = *(const float4*)&As[kk][ty * TM];
            float4 a1 = *(const float4*)&As[kk][ty * TM + 4];
            float4 b0 = *(const float4*)&Bs[kk][tx * TN];
            a[0]=a0.x; a[1]=a0.y; a[2]=a0.z; a[3]=a0.w;
            a[4]=a1.x; a[5]=a1.y; a[6]=a1.z; a[7]=a1.w;
            b[0]=b0.x; b[1]=b0.y; b[2]=b0.z; b[3]=b0.w;
            #pragma unroll
            for (int i = 0; i < TM; i++)
                #pragma unroll
                for (int j = 0; j < TN; j++)
                    acc[i][j] = fmaf(a[i], b[j], acc[i][j]);
        }
        __syncthreads();

        if (((k0 + BK) & (SPLITK_CHUNK - 1)) == 0) {
            #pragma unroll
            for (int i = 0; i < TM; i++)
                #pragma unroll
                for (int j = 0; j < TN; j++) { tot[i][j] += acc[i][j]; acc[i][j] = 0.f; }
        }
    }

    #pragma unroll
    for (int i = 0; i < TM; i++) {
        const int r = row0 + ty * TM + i;
        #pragma unroll
        for (int j = 0; j < TN; j++) {
            const int col = bxl * BN + tx * TN + j;
            float y = tot[i][j];
            unsigned m = 0; float vm = 0.f;
            #pragma unroll
            for (int t = 0; t < TSTEPS; t++) {
                vm += y;
                if (vm - 1.0f >= 0.f) { m |= (1u << t); vm = 0.f; }
            }
            C[(size_t)r * N + col] = m;
        }
    }
}

// ---------------------------------------------------------------------------
// Big GEMM (NT), 128x128 tile, 8x8/thread, BK=8, DOUBLE-BUFFERED smem.
// Per-element accumulation order identical to R7 (sequential ascending k).
//   MODE 1: FFN spike counts (N=HIDDEN; by<4 -> w3/c3 M=512; else w1/c1 M=256)
//   MODE 2: plain f32 store (per-t wo GEMM, M=2560, N=DIM)
//   MODE 3: w2, A = gate(c1,c3p,c3n) on the fly; out = addv + y
// ---------------------------------------------------------------------------
#define BM2 128
#define BN2 128
#define BK2 8

template<int MODE>
__global__ __launch_bounds__(256)
void gemm2_kernel(const float* __restrict__ A,
                  const float* __restrict__ A2,
                  const float* __restrict__ A3,
                  const float* __restrict__ B0,
                  const float* __restrict__ B1,
                  void* __restrict__ C0, void* __restrict__ C1,
                  const float* __restrict__ addv, int K)
{
    __shared__ float As[2][BK2][BM2];
    __shared__ float Bs[2][BK2][BN2];

    const int bx = blockIdx.x, by = blockIdx.y;
    const float* B; void* C; int N, row0;
    if (MODE == 1) {
        N = HIDDEN;
        if (by < 4) { B = B0; C = C0; row0 = by * BM2; }
        else        { B = B1; C = C1; row0 = (by - 4) * BM2; }
    } else {
        N = DIM; B = B0; C = C0; row0 = by * BM2;
    }

    const int tid = threadIdx.x;
    const int tx = tid & 15;        // 16 col groups x 8
    const int ty = tid >> 4;        // 16 row groups x 8
    const int lrow  = tid >> 1;     // 0..127
    const int lcol4 = (tid & 1) * 4;

    const size_t aoff0 = (size_t)(row0 + lrow) * K + lcol4;
    const float* Aptr  = A + aoff0;
    const float* A2ptr = (MODE == 3) ? (A2 + aoff0) : nullptr;
    const float* A3ptr = (MODE == 3) ? (A3 + aoff0) : nullptr;
    const float* Bptr  = B + (size_t)(bx * BN2 + lrow) * K + lcol4;

    float acc[8][8];
    #pragma unroll
    for (int i = 0; i < 8; i++)
        #pragma unroll
        for (int j = 0; j < 8; j++) acc[i][j] = 0.f;

    // ---- load helper (macro to keep pointer advancement uniform) ----
    #define LOAD_AB(AV, BV)                                                    \
        do {                                                                   \
            if (MODE == 3) {                                                   \
                float4 c1v = *(const float4*)Aptr;                             \
                float4 pv  = *(const float4*)A2ptr;                            \
                float4 nv  = *(const float4*)A3ptr;                            \
                (AV).x = (c1v.x / 10.0f) * ((pv.x - nv.x) / 10.0f);            \
                (AV).y = (c1v.y / 10.0f) * ((pv.y - nv.y) / 10.0f);            \
                (AV).z = (c1v.z / 10.0f) * ((pv.z - nv.z) / 10.0f);            \
                (AV).w = (c1v.w / 10.0f) * ((pv.w - nv.w) / 10.0f);            \
                A2ptr += BK2; A3ptr += BK2;                                    \
            } else {                                                           \
                (AV) = *(const float4*)Aptr;                                   \
            }                                                                  \
            Aptr += BK2;                                                       \
            (BV) = *(const float4*)Bptr;                                       \
            Bptr += BK2;                                                       \
        } while (0)

    #define STORE_AB(BUF, AV, BV)                                              \
        do {                                                                   \
            As[BUF][lcol4 + 0][lrow] = (AV).x;                                 \
            As[BUF][lcol4 + 1][lrow] = (AV).y;                                 \
            As[BUF][lcol4 + 2][lrow] = (AV).z;                                 \
            As[BUF][lcol4 + 3][lrow] = (AV).w;                                 \
            Bs[BUF][lcol4 + 0][lrow] = (BV).x;                                 \
            Bs[BUF][lcol4 + 1][lrow] = (BV).y;                                 \
            Bs[BUF][lcol4 + 2][lrow] = (BV).z;                                 \
            Bs[BUF][lcol4 + 3][lrow] = (BV).w;                                 \
        } while (0)

    // preload tile 0
    {
        float4 av, bv;
        LOAD_AB(av, bv);
        STORE_AB(0, av, bv);
    }
    __syncthreads();

    int buf = 0;
    for (int k0 = 0; k0 < K; k0 += BK2) {
        const bool has_next = (k0 + BK2 < K);
        float4 nav, nbv;
        if (has_next) LOAD_AB(nav, nbv);

        #pragma unroll
        for (int kk = 0; kk < BK2; kk++) {
            float a[8], b[8];
            float4 a0 = *(const float4*)&As[buf][kk][ty * 8];
            float4 a1 = *(const float4*)&As[buf][kk][ty * 8 + 4];
            float4 b0 = *(const float4*)&Bs[buf][kk][tx * 8];
            float4 b1 = *(const float4*)&Bs[buf][kk][tx * 8 + 4];
            a[0]=a0.x; a[1]=a0.y; a[2]=a0.z; a[3]=a0.w;
            a[4]=a1.x; a[5]=a1.y; a[6]=a1.z; a[7]=a1.w;
            b[0]=b0.x; b[1]=b0.y; b[2]=b0.z; b[3]=b0.w;
            b[4]=b1.x; b[5]=b1.y; b[6]=b1.z; b[7]=b1.w;
            #pragma unroll
            for (int i = 0; i < 8; i++)
                #pragma unroll
                for (int j = 0; j < 8; j++)
                    acc[i][j] = fmaf(a[i], b[j], acc[i][j]);
        }

        if (has_next) STORE_AB(buf ^ 1, nav, nbv);
        __syncthreads();
        buf ^= 1;
    }
    #undef LOAD_AB
    #undef STORE_AB

    #pragma unroll
    for (int i = 0; i < 8; i++) {
        const int r = row0 + ty * 8 + i;
        #pragma unroll
        for (int j = 0; j < 8; j++) {
            const int col = bx * BN2 + tx * 8 + j;
            const size_t idx = (size_t)r * N + col;
            float y = acc[i][j];
            if (MODE == 1) {
                int cnt = 0; float vm = 0.f;
                #pragma unroll
                for (int t = 0; t < TSTEPS; t++) {
                    vm += y;
                    if (vm - 1.0f >= 0.f) { cnt++; vm = 0.f; }
                }
                ((float*)C)[idx] = (float)cnt;
            } else if (MODE == 2) {
                ((float*)C)[idx] = y;
            } else {
                ((float*)C)[idx] = addv[idx] + y;
            }
        }
    }
}

// ---------------------------------------------------------------------------
// Spike attention (bit-frozen since R7): exact integer math, per-t planes.
// ---------------------------------------------------------------------------
__global__ void attn_kernel(const unsigned* __restrict__ qm,
                            const unsigned* __restrict__ km,
                            const unsigned* __restrict__ vm,
                            float* __restrict__ xat)
{
    __shared__ unsigned sq[128 * 33];
    __shared__ unsigned sk[128 * 9];
    __shared__ unsigned sv[8 * 128];
    __shared__ int      S[NHEAD * 8];

    const int n   = blockIdx.x;
    const int tid = threadIdx.x;

    for (int idx = tid; idx < NHEAD * HDIM; idx += 128) {
        const int i = idx >> 7, d = idx & 127;
        sq[d * 33 + i] = qm[(size_t)n * DIM + idx] | (qm[(size_t)(n + NTOK) * DIM + idx] << 16);
    }
    for (int idx = tid; idx < 8 * HDIM; idx += 128) {
        const int j = idx >> 7, d = idx & 127;
        sk[d * 9 + j] = km[(size_t)n * KVDIM + idx] | (km[(size_t)(n + NTOK) * KVDIM + idx] << 16);
        sv[idx]       = vm[(size_t)n * KVDIM + idx] | (vm[(size_t)(n + NTOK) * KVDIM + idx] << 16);
    }
    __syncthreads();

    for (int t = 0; t < TSTEPS; t++) {
        #pragma unroll
        for (int e0 = 0; e0 < 2; e0++) {
            const int e = tid + e0 * 128;
            const int i = e >> 3, j = e & 7;
            int s = 0;
            for (int d2 = 0; d2 < HDIM; d2++) {
                const unsigned q = sq[d2 * 33 + i];
                const unsigned k = sk[d2 * 9 + j];
                const int qv = (int)((q >> t) & 1u) - (int)((q >> (t + 16)) & 1u);
                const int kv = (int)((k >> t) & 1u) - (int)((k >> (t + 16)) & 1u);
                s += qv * kv;
            }
            S[e] = s;
        }
        __syncthreads();

        {
            const int d2 = tid;
            int vv[8];
            #pragma unroll
            for (int j = 0; j < 8; j++) {
                const unsigned v = sv[j * 128 + d2];
                vv[j] = (int)((v >> t) & 1u) - (int)((v >> (t + 16)) & 1u);
            }
            float* orow = xat + ((size_t)t * NTOK + n) * DIM + (size_t)d2 * NHEAD;
            #pragma unroll
            for (int i = 0; i < NHEAD; i++) {
                int s = 0;
                #pragma unroll
                for (int j = 0; j < 8; j++) s += S[i * 8 + j] * vv[j];
                orow[i] = (float)s * 0.5f;
            }
        }
        __syncthreads();
    }
}

// ---------------------------------------------------------------------------
// h = x + mean_t(y_t) (bit-frozen)
// ---------------------------------------------------------------------------
__global__ void wo_mean_kernel(const float* __restrict__ yt,
                               const float* __restrict__ x,
                               float* __restrict__ h)
{
    const int idx = blockIdx.x * blockDim.x + threadIdx.x;
    if (idx >= NTOK * DIM) return;
    float s = 0.f;
    #pragma unroll
    for (int t = 0; t < TSTEPS; t++)
        s += yt[(size_t)t * NTOK * DIM + idx];
    h[idx] = x[idx] + s / 10.0f;
}

// ---------------------------------------------------------------------------
// Launch
// ---------------------------------------------------------------------------
extern "C" void kernel_launch(void* const* d_in, const int* in_sizes, int n_in,
                              void* d_out, int out_size)
{
    const float* x           = (const float*)d_in[0];
    const float* attn_norm_w = (const float*)d_in[2];
    const float* ffn_norm_w  = (const float*)d_in[3];
    const float* wq          = (const float*)d_in[4];
    const float* wk          = (const float*)d_in[5];
    const float* wv          = (const float*)d_in[6];
    const float* wo          = (const float*)d_in[7];
    const float* w1          = (const float*)d_in[8];
    const float* w2          = (const float*)d_in[9];
    const float* w3          = (const float*)d_in[10];
    float* out = (float*)d_out;

    float *xs, *hs, *xat, *yt, *h, *c3, *c1;
    unsigned *qm, *km, *vm;
    cudaGetSymbolAddress((void**)&xs,  g_xs);
    cudaGetSymbolAddress((void**)&hs,  g_hs);
    cudaGetSymbolAddress((void**)&qm,  g_qm);
    cudaGetSymbolAddress((void**)&km,  g_km);
    cudaGetSymbolAddress((void**)&vm,  g_vm);
    cudaGetSymbolAddress((void**)&xat, g_xat);
    cudaGetSymbolAddress((void**)&yt,  g_yt);
    cudaGetSymbolAddress((void**)&h,   g_h);
    cudaGetSymbolAddress((void**)&c3,  g_c3);
    cudaGetSymbolAddress((void**)&c1,  g_c1);

    // 1) attn rmsnorm + stacked relu
    rmsnorm_relu_kernel<<<NTOK, 1024>>>(x, attn_norm_w, xs);

    // 2) fused QKV spike-mask projections (split-K=4, bit-frozen)
    gemm_qkv_kernel<<<dim3(96, 4), 256>>>(xs, wq, wk, wv, qm, km, vm, DIM);

    // 3) exact spike attention -> per-timestep planes
    attn_kernel<<<NTOK, 128>>>(qm, km, vm, xat);

    // 4) per-t wo GEMM: yt[t,n,:] = xa_t @ wo^T   (M=2560) — new fast path
    gemm2_kernel<2><<<dim3(32, 20), 256>>>(xat, nullptr, nullptr,
                                           wo, nullptr, yt, nullptr, nullptr, DIM);

    // 5) h = x + mean_t(y_t)
    wo_mean_kernel<<<(NTOK * DIM + 255) / 256, 256>>>(yt, x, h);

    // 6) ffn rmsnorm + stacked relu
    rmsnorm_relu_kernel<<<NTOK, 1024>>>(h, ffn_norm_w, hs);

    // 7) fused FFN spike-count projections: w3 (M=512) + w1 (M=256) — fast path
    gemm2_kernel<1><<<dim3(112, 6), 256>>>(hs, nullptr, nullptr,
                                           w3, w1, c3, c1, nullptr, DIM);

    // 8) out = h + gate(c1,c3) @ w2^T — fast path
    gemm2_kernel<3><<<dim3(32, 2), 256>>>(c1, c3, c3 + (size_t)NTOK * HIDDEN,
                                          w2, nullptr, out, nullptr, h, HIDDEN);
}

// round 9
// speedup vs baseline: 1.6526x; 1.6397x over previous
#include <cuda_runtime.h>
#include <cstdint>

// ---------------------------------------------------------------------------
// Problem constants
// ---------------------------------------------------------------------------
#define NTOK   256
#define DIM    4096
#define HIDDEN 14336
#define KVDIM  1024
#define NHEAD  32
#define HDIM   128
#define TSTEPS 10

// ---------------------------------------------------------------------------
// Scratch (device globals)
// ---------------------------------------------------------------------------
__device__ float    g_xs [2 * NTOK * DIM];
__device__ float    g_hs [2 * NTOK * DIM];
__device__ unsigned g_qm [2 * NTOK * DIM];
__device__ unsigned g_km [2 * NTOK * KVDIM];
__device__ unsigned g_vm [2 * NTOK * KVDIM];
__device__ float    g_xat[TSTEPS * NTOK * DIM];
__device__ float    g_yt [TSTEPS * NTOK * DIM];
__device__ float    g_h  [NTOK * DIM];
__device__ float    g_c3 [2 * NTOK * HIDDEN];
__device__ float    g_c1 [NTOK * HIDDEN];
__device__ float    g_gate[NTOK * HIDDEN];

// ---------------------------------------------------------------------------
// RMSNorm + stacked relu (bit-frozen)
// ---------------------------------------------------------------------------
__global__ __launch_bounds__(1024)
void rmsnorm_relu_kernel(const float* __restrict__ x,
                         const float* __restrict__ w,
                         float* __restrict__ out)
{
    const int n = blockIdx.x;
    const int t = threadIdx.x;
    const float* xr = x + (size_t)n * DIM;

    float acc = 0.f;
    #pragma unroll
    for (int i = 0; i < 2; i++) {
        float2 v = *(const float2*)(xr + 2 * t + i * 2048);
        acc += v.x * v.x;
        acc += v.y * v.y;
    }
    #pragma unroll
    for (int o = 16; o > 0; o >>= 1)
        acc += __shfl_down_sync(0xffffffffu, acc, o);

    __shared__ float sw[32];
    __shared__ float sres;
    const int lane = t & 31, wid = t >> 5;
    if (lane == 0) sw[wid] = acc;
    __syncthreads();
    if (wid == 0) {
        float v = sw[lane];
        #pragma unroll
        for (int o = 16; o > 0; o >>= 1)
            v += __shfl_down_sync(0xffffffffu, v, o);
        if (lane == 0) sres = v;
    }
    __syncthreads();

    const float rs = rsqrtf(sres * (1.0f / 4096.0f) + 1e-5f);
    #pragma unroll
    for (int i = 0; i < 4; i++) {
        const int c = t + i * 1024;
        float v = xr[c] * rs * w[c];
        out[(size_t)n * DIM + c]          = fmaxf(v, 0.f);
        out[(size_t)(n + NTOK) * DIM + c] = fmaxf(-v, 0.f);
    }
}

// ---------------------------------------------------------------------------
// QKV GEMM: split-K=4 emulation. Per-element k-order IDENTICAL to R7 pass:
// sequential ascending k, fold into tot at every k%1024==0 boundary.
// Tile 128x64, BK=16, 8x4/thread, 256 threads, double-buffered.
// ---------------------------------------------------------------------------
#define QBM 128
#define QBN 64
#define QBK 16
#define SPLITK_CHUNK 1024

__global__ __launch_bounds__(256, 2)
void gemm_qkv_kernel(const float* __restrict__ A,
                     const float* __restrict__ B0,
                     const float* __restrict__ B1,
                     const float* __restrict__ B2,
                     unsigned* __restrict__ C0, unsigned* __restrict__ C1,
                     unsigned* __restrict__ C2, int K)
{
    __shared__ float As[2][QBK][QBM];
    __shared__ float Bs[2][QBK][QBN];

    const int bx = blockIdx.x, by = blockIdx.y;
    const float* B; unsigned* C; int N, bxl;
    const int row0 = by * QBM;
    if (bx < 64)      { B = B0; C = C0; N = DIM;   bxl = bx; }
    else if (bx < 80) { B = B1; C = C1; N = KVDIM; bxl = bx - 64; }
    else              { B = B2; C = C2; N = KVDIM; bxl = bx - 80; }

    const int tid = threadIdx.x;
    const int tx = tid & 15;            // col group x4
    const int ty = tid >> 4;            // row group x8

    const int lrowA = tid >> 1;         // 0..127
    const int lcolA = (tid & 1) * 8;    // 0 or 8  (2 float4)
    const int lrowB = tid >> 2;         // 0..63
    const int lcolB = (tid & 3) * 4;    // 0,4,8,12 (1 float4)

    const float* Aptr = A + (size_t)(row0 + lrowA) * K + lcolA;
    const float* Bptr = B + (size_t)(bxl * QBN + lrowB) * K + lcolB;

    float acc[8][4], tot[8][4];
    #pragma unroll
    for (int i = 0; i < 8; i++)
        #pragma unroll
        for (int j = 0; j < 4; j++) { acc[i][j] = 0.f; tot[i][j] = 0.f; }

    float4 a0s, a1s, b0s;
    #define QLOAD()                                                            \
        do {                                                                   \
            a0s = *(const float4*)Aptr;                                        \
            a1s = *(const float4*)(Aptr + 4);                                  \
            b0s = *(const float4*)Bptr;                                        \
            Aptr += QBK; Bptr += QBK;                                          \
        } while (0)
    #define QSTORE(BUF)                                                        \
        do {                                                                   \
            As[BUF][lcolA + 0][lrowA] = a0s.x; As[BUF][lcolA + 1][lrowA] = a0s.y; \
            As[BUF][lcolA + 2][lrowA] = a0s.z; As[BUF][lcolA + 3][lrowA] = a0s.w; \
            As[BUF][lcolA + 4][lrowA] = a1s.x; As[BUF][lcolA + 5][lrowA] = a1s.y; \
            As[BUF][lcolA + 6][lrowA] = a1s.z; As[BUF][lcolA + 7][lrowA] = a1s.w; \
            Bs[BUF][lcolB + 0][lrowB] = b0s.x; Bs[BUF][lcolB + 1][lrowB] = b0s.y; \
            Bs[BUF][lcolB + 2][lrowB] = b0s.z; Bs[BUF][lcolB + 3][lrowB] = b0s.w; \
        } while (0)

    QLOAD(); QSTORE(0);
    __syncthreads();

    int buf = 0;
    for (int k0 = 0; k0 < K; k0 += QBK) {
        const bool has_next = (k0 + QBK < K);
        if (has_next) QLOAD();

        #pragma unroll
        for (int kk = 0; kk < QBK; kk++) {
            float a[8], b[4];
            float4 a0 = *(const float4*)&As[buf][kk][ty * 8];
            float4 a1 = *(const float4*)&As[buf][kk][ty * 8 + 4];
            float4 b0 = *(const float4*)&Bs[buf][kk][tx * 4];
            a[0]=a0.x; a[1]=a0.y; a[2]=a0.z; a[3]=a0.w;
            a[4]=a1.x; a[5]=a1.y; a[6]=a1.z; a[7]=a1.w;
            b[0]=b0.x; b[1]=b0.y; b[2]=b0.z; b[3]=b0.w;
            #pragma unroll
            for (int i = 0; i < 8; i++)
                #pragma unroll
                for (int j = 0; j < 4; j++)
                    acc[i][j] = fmaf(a[i], b[j], acc[i][j]);
        }

        if (((k0 + QBK) & (SPLITK_CHUNK - 1)) == 0) {
            #pragma unroll
            for (int i = 0; i < 8; i++)
                #pragma unroll
                for (int j = 0; j < 4; j++) { tot[i][j] += acc[i][j]; acc[i][j] = 0.f; }
        }

        if (has_next) QSTORE(buf ^ 1);
        __syncthreads();
        buf ^= 1;
    }
    #undef QLOAD
    #undef QSTORE

    #pragma unroll
    for (int i = 0; i < 8; i++) {
        const int r = row0 + ty * 8 + i;
        #pragma unroll
        for (int j = 0; j < 4; j++) {
            const int col = bxl * QBN + tx * 4 + j;
            float y = tot[i][j];
            unsigned m = 0; float vm = 0.f;
            #pragma unroll
            for (int t = 0; t < TSTEPS; t++) {
                vm += y;
                if (vm - 1.0f >= 0.f) { m |= (1u << t); vm = 0.f; }
            }
            C[(size_t)r * N + col] = m;
        }
    }
}

// ---------------------------------------------------------------------------
// Big GEMM (NT), 128x128 tile, 8x8/thread, BK=16, double-buffered.
// Sequential ascending k per output (bit-identical to R7).
//   MODE 1: FFN spike counts (N=HIDDEN; by<4 -> w3/c3 M=512; else w1/c1 M=256)
//   MODE 2: plain f32 store (per-t wo GEMM, M=2560, N=DIM)
// ---------------------------------------------------------------------------
#define BM2 128
#define BN2 128
#define BK2 16

template<int MODE>
__global__ __launch_bounds__(256, 2)
void gemm2_kernel(const float* __restrict__ A,
                  const float* __restrict__ B0,
                  const float* __restrict__ B1,
                  void* __restrict__ C0, void* __restrict__ C1, int K)
{
    __shared__ float As[2][BK2][BM2];
    __shared__ float Bs[2][BK2][BN2];

    const int bx = blockIdx.x, by = blockIdx.y;
    const float* B; void* C; int N, row0;
    if (MODE == 1) {
        N = HIDDEN;
        if (by < 4) { B = B0; C = C0; row0 = by * BM2; }
        else        { B = B1; C = C1; row0 = (by - 4) * BM2; }
    } else {
        N = DIM; B = B0; C = C0; row0 = by * BM2;
    }

    const int tid = threadIdx.x;
    const int tx = tid & 15;
    const int ty = tid >> 4;
    const int lrow = tid >> 1;          // 0..127
    const int lcol = (tid & 1) * 8;     // 0 or 8

    const float* Aptr = A + (size_t)(row0 + lrow) * K + lcol;
    const float* Bptr = B + (size_t)(bx * BN2 + lrow) * K + lcol;

    float acc[8][8];
    #pragma unroll
    for (int i = 0; i < 8; i++)
        #pragma unroll
        for (int j = 0; j < 8; j++) acc[i][j] = 0.f;

    float4 a0s, a1s, b0s, b1s;
    #define GLOAD()                                                            \
        do {                                                                   \
            a0s = *(const float4*)Aptr;                                        \
            a1s = *(const float4*)(Aptr + 4);                                  \
            b0s = *(const float4*)Bptr;                                        \
            b1s = *(const float4*)(Bptr + 4);                                  \
            Aptr += BK2; Bptr += BK2;                                          \
        } while (0)
    #define GSTORE(BUF)                                                        \
        do {                                                                   \
            As[BUF][lcol + 0][lrow] = a0s.x; As[BUF][lcol + 1][lrow] = a0s.y;  \
            As[BUF][lcol + 2][lrow] = a0s.z; As[BUF][lcol + 3][lrow] = a0s.w;  \
            As[BUF][lcol + 4][lrow] = a1s.x; As[BUF][lcol + 5][lrow] = a1s.y;  \
            As[BUF][lcol + 6][lrow] = a1s.z; As[BUF][lcol + 7][lrow] = a1s.w;  \
            Bs[BUF][lcol + 0][lrow] = b0s.x; Bs[BUF][lcol + 1][lrow] = b0s.y;  \
            Bs[BUF][lcol + 2][lrow] = b0s.z; Bs[BUF][lcol + 3][lrow] = b0s.w;  \
            Bs[BUF][lcol + 4][lrow] = b1s.x; Bs[BUF][lcol + 5][lrow] = b1s.y;  \
            Bs[BUF][lcol + 6][lrow] = b1s.z; Bs[BUF][lcol + 7][lrow] = b1s.w;  \
        } while (0)

    GLOAD(); GSTORE(0);
    __syncthreads();

    int buf = 0;
    for (int k0 = 0; k0 < K; k0 += BK2) {
        const bool has_next = (k0 + BK2 < K);
        if (has_next) GLOAD();

        #pragma unroll
        for (int kk = 0; kk < BK2; kk++) {
            float a[8], b[8];
            float4 a0 = *(const float4*)&As[buf][kk][ty * 8];
            float4 a1 = *(const float4*)&As[buf][kk][ty * 8 + 4];
            float4 b0 = *(const float4*)&Bs[buf][kk][tx * 8];
            float4 b1 = *(const float4*)&Bs[buf][kk][tx * 8 + 4];
            a[0]=a0.x; a[1]=a0.y; a[2]=a0.z; a[3]=a0.w;
            a[4]=a1.x; a[5]=a1.y; a[6]=a1.z; a[7]=a1.w;
            b[0]=b0.x; b[1]=b0.y; b[2]=b0.z; b[3]=b0.w;
            b[4]=b1.x; b[5]=b1.y; b[6]=b1.z; b[7]=b1.w;
            #pragma unroll
            for (int i = 0; i < 8; i++)
                #pragma unroll
                for (int j = 0; j < 8; j++)
                    acc[i][j] = fmaf(a[i], b[j], acc[i][j]);
        }

        if (has_next) GSTORE(buf ^ 1);
        __syncthreads();
        buf ^= 1;
    }
    #undef GLOAD
    #undef GSTORE

    #pragma unroll
    for (int i = 0; i < 8; i++) {
        const int r = row0 + ty * 8 + i;
        #pragma unroll
        for (int j = 0; j < 8; j++) {
            const int col = bx * BN2 + tx * 8 + j;
            const size_t idx = (size_t)r * N + col;
            float y = acc[i][j];
            if (MODE == 1) {
                int cnt = 0; float vm = 0.f;
                #pragma unroll
                for (int t = 0; t < TSTEPS; t++) {
                    vm += y;
                    if (vm - 1.0f >= 0.f) { cnt++; vm = 0.f; }
                }
                ((float*)C)[idx] = (float)cnt;
            } else {
                ((float*)C)[idx] = y;
            }
        }
    }
}

// ---------------------------------------------------------------------------
// w2 GEMM: 64x64 tile (256 CTAs for full-chip utilization), BK=32, 4x4/thread.
// Sequential ascending k; epilogue out = h + y. A = precomputed gate.
// ---------------------------------------------------------------------------
#define WBM 64
#define WBN 64
#define WBK 32

__global__ __launch_bounds__(256)
void gemm_w2_kernel(const float* __restrict__ A,
                    const float* __restrict__ B,
                    float* __restrict__ C,
                    const float* __restrict__ addv, int K)
{
    __shared__ float As[2][WBK][WBM];
    __shared__ float Bs[2][WBK][WBN];

    const int bx = blockIdx.x, by = blockIdx.y;
    const int row0 = by * WBM;
    const int tid = threadIdx.x;
    const int tx = tid & 15;
    const int ty = tid >> 4;
    const int lrow = tid >> 2;          // 0..63
    const int lcol = (tid & 3) * 8;     // 0,8,16,24

    const float* Aptr = A + (size_t)(row0 + lrow) * K + lcol;
    const float* Bptr = B + (size_t)(bx * WBN + lrow) * K + lcol;

    float acc[4][4];
    #pragma unroll
    for (int i = 0; i < 4; i++)
        #pragma unroll
        for (int j = 0; j < 4; j++) acc[i][j] = 0.f;

    float4 a0s, a1s, b0s, b1s;
    #define WLOAD()                                                            \
        do {                                                                   \
            a0s = *(const float4*)Aptr;                                        \
            a1s = *(const float4*)(Aptr + 4);                                  \
            b0s = *(const float4*)Bptr;                                        \
            b1s = *(const float4*)(Bptr + 4);                                  \
            Aptr += WBK; Bptr += WBK;                                          \
        } while (0)
    #define WSTORE(BUF)                                                        \
        do {                                                                   \
            As[BUF][lcol + 0][lrow] = a0s.x; As[BUF][lcol + 1][lrow] = a0s.y;  \
            As[BUF][lcol + 2][lrow] = a0s.z; As[BUF][lcol + 3][lrow] = a0s.w;  \
            As[BUF][lcol + 4][lrow] = a1s.x; As[BUF][lcol + 5][lrow] = a1s.y;  \
            As[BUF][lcol + 6][lrow] = a1s.z; As[BUF][lcol + 7][lrow] = a1s.w;  \
            Bs[BUF][lcol + 0][lrow] = b0s.x; Bs[BUF][lcol + 1][lrow] = b0s.y;  \
            Bs[BUF][lcol + 2][lrow] = b0s.z; Bs[BUF][lcol + 3][lrow] = b0s.w;  \
            Bs[BUF][lcol + 4][lrow] = b1s.x; Bs[BUF][lcol + 5][lrow] = b1s.y;  \
            Bs[BUF][lcol + 6][lrow] = b1s.z; Bs[BUF][lcol + 7][lrow] = b1s.w;  \
        } while (0)

    WLOAD(); WSTORE(0);
    __syncthreads();

    int buf = 0;
    for (int k0 = 0; k0 < K; k0 += WBK) {
        const bool has_next = (k0 + WBK < K);
        if (has_next) WLOAD();

        #pragma unroll
        for (int kk = 0; kk < WBK; kk++) {
            float a[4], b[4];
            float4 a0 = *(const float4*)&As[buf][kk][ty * 4];
            float4 b0 = *(const float4*)&Bs[buf][kk][tx * 4];
            a[0]=a0.x; a[1]=a0.y; a[2]=a0.z; a[3]=a0.w;
            b[0]=b0.x; b[1]=b0.y; b[2]=b0.z; b[3]=b0.w;
            #pragma unroll
            for (int i = 0; i < 4; i++)
                #pragma unroll
                for (int j = 0; j < 4; j++)
                    acc[i][j] = fmaf(a[i], b[j], acc[i][j]);
        }

        if (has_next) WSTORE(buf ^ 1);
        __syncthreads();
        buf ^= 1;
    }
    #undef WLOAD
    #undef WSTORE

    #pragma unroll
    for (int i = 0; i < 4; i++) {
        const int r = row0 + ty * 4 + i;
        #pragma unroll
        for (int j = 0; j < 4; j++) {
            const int col = bx * WBN + tx * 4 + j;
            const size_t idx = (size_t)r * DIM + col;
            C[idx] = addv[idx] + acc[i][j];
        }
    }
}

// ---------------------------------------------------------------------------
// gate = (c1/10) * ((c3p - c3n)/10)   — same formula/order as before (exact)
// ---------------------------------------------------------------------------
__global__ void gate_kernel(const float* __restrict__ c1,
                            const float* __restrict__ c3p,
                            const float* __restrict__ c3n,
                            float* __restrict__ g)
{
    const int i = blockIdx.x * blockDim.x + threadIdx.x;
    if (i < NTOK * HIDDEN)
        g[i] = (c1[i] / 10.0f) * ((c3p[i] - c3n[i]) / 10.0f);
}

// ---------------------------------------------------------------------------
// Spike attention (bit-frozen)
// ---------------------------------------------------------------------------
__global__ void attn_kernel(const unsigned* __restrict__ qm,
                            const unsigned* __restrict__ km,
                            const unsigned* __restrict__ vm,
                            float* __restrict__ xat)
{
    __shared__ unsigned sq[128 * 33];
    __shared__ unsigned sk[128 * 9];
    __shared__ unsigned sv[8 * 128];
    __shared__ int      S[NHEAD * 8];

    const int n   = blockIdx.x;
    const int tid = threadIdx.x;

    for (int idx = tid; idx < NHEAD * HDIM; idx += 128) {
        const int i = idx >> 7, d = idx & 127;
        sq[d * 33 + i] = qm[(size_t)n * DIM + idx] | (qm[(size_t)(n + NTOK) * DIM + idx] << 16);
    }
    for (int idx = tid; idx < 8 * HDIM; idx += 128) {
        const int j = idx >> 7, d = idx & 127;
        sk[d * 9 + j] = km[(size_t)n * KVDIM + idx] | (km[(size_t)(n + NTOK) * KVDIM + idx] << 16);
        sv[idx]       = vm[(size_t)n * KVDIM + idx] | (vm[(size_t)(n + NTOK) * KVDIM + idx] << 16);
    }
    __syncthreads();

    for (int t = 0; t < TSTEPS; t++) {
        #pragma unroll
        for (int e0 = 0; e0 < 2; e0++) {
            const int e = tid + e0 * 128;
            const int i = e >> 3, j = e & 7;
            int s = 0;
            for (int d2 = 0; d2 < HDIM; d2++) {
                const unsigned q = sq[d2 * 33 + i];
                const unsigned k = sk[d2 * 9 + j];
                const int qv = (int)((q >> t) & 1u) - (int)((q >> (t + 16)) & 1u);
                const int kv = (int)((k >> t) & 1u) - (int)((k >> (t + 16)) & 1u);
                s += qv * kv;
            }
            S[e] = s;
        }
        __syncthreads();

        {
            const int d2 = tid;
            int vv[8];
            #pragma unroll
            for (int j = 0; j < 8; j++) {
                const unsigned v = sv[j * 128 + d2];
                vv[j] = (int)((v >> t) & 1u) - (int)((v >> (t + 16)) & 1u);
            }
            float* orow = xat + ((size_t)t * NTOK + n) * DIM + (size_t)d2 * NHEAD;
            #pragma unroll
            for (int i = 0; i < NHEAD; i++) {
                int s = 0;
                #pragma unroll
                for (int j = 0; j < 8; j++) s += S[i * 8 + j] * vv[j];
                orow[i] = (float)s * 0.5f;
            }
        }
        __syncthreads();
    }
}

// ---------------------------------------------------------------------------
// h = x + mean_t(y_t) (bit-frozen)
// ---------------------------------------------------------------------------
__global__ void wo_mean_kernel(const float* __restrict__ yt,
                               const float* __restrict__ x,
                               float* __restrict__ h)
{
    const int idx = blockIdx.x * blockDim.x + threadIdx.x;
    if (idx >= NTOK * DIM) return;
    float s = 0.f;
    #pragma unroll
    for (int t = 0; t < TSTEPS; t++)
        s += yt[(size_t)t * NTOK * DIM + idx];
    h[idx] = x[idx] + s / 10.0f;
}

// ---------------------------------------------------------------------------
// Launch
// ---------------------------------------------------------------------------
extern "C" void kernel_launch(void* const* d_in, const int* in_sizes, int n_in,
                              void* d_out, int out_size)
{
    const float* x           = (const float*)d_in[0];
    const float* attn_norm_w = (const float*)d_in[2];
    const float* ffn_norm_w  = (const float*)d_in[3];
    const float* wq          = (const float*)d_in[4];
    const float* wk          = (const float*)d_in[5];
    const float* wv          = (const float*)d_in[6];
    const float* wo          = (const float*)d_in[7];
    const float* w1          = (const float*)d_in[8];
    const float* w2          = (const float*)d_in[9];
    const float* w3          = (const float*)d_in[10];
    float* out = (float*)d_out;

    float *xs, *hs, *xat, *yt, *h, *c3, *c1, *gate;
    unsigned *qm, *km, *vm;
    cudaGetSymbolAddress((void**)&xs,   g_xs);
    cudaGetSymbolAddress((void**)&hs,   g_hs);
    cudaGetSymbolAddress((void**)&qm,   g_qm);
    cudaGetSymbolAddress((void**)&km,   g_km);
    cudaGetSymbolAddress((void**)&vm,   g_vm);
    cudaGetSymbolAddress((void**)&xat,  g_xat);
    cudaGetSymbolAddress((void**)&yt,   g_yt);
    cudaGetSymbolAddress((void**)&h,    g_h);
    cudaGetSymbolAddress((void**)&c3,   g_c3);
    cudaGetSymbolAddress((void**)&c1,   g_c1);
    cudaGetSymbolAddress((void**)&gate, g_gate);

    // 1) attn rmsnorm + stacked relu
    rmsnorm_relu_kernel<<<NTOK, 1024>>>(x, attn_norm_w, xs);

    // 2) fused QKV spike-mask projections (split-K=4, double-buffered)
    gemm_qkv_kernel<<<dim3(96, 4), 256>>>(xs, wq, wk, wv, qm, km, vm, DIM);

    // 3) exact spike attention -> per-timestep planes
    attn_kernel<<<NTOK, 128>>>(qm, km, vm, xat);

    // 4) per-t wo GEMM: yt = xat @ wo^T  (M=2560)
    gemm2_kernel<2><<<dim3(32, 20), 256>>>(xat, wo, nullptr, yt, nullptr, DIM);

    // 5) h = x + mean_t(y_t)
    wo_mean_kernel<<<(NTOK * DIM + 255) / 256, 256>>>(yt, x, h);

    // 6) ffn rmsnorm + stacked relu
    rmsnorm_relu_kernel<<<NTOK, 1024>>>(h, ffn_norm_w, hs);

    // 7) fused FFN spike-count projections: w3 (M=512) + w1 (M=256)
    gemm2_kernel<1><<<dim3(112, 6), 256>>>(hs, w3, w1, c3, c1, DIM);

    // 8) gate (elementwise, bit-exact same formula)
    gate_kernel<<<(NTOK * HIDDEN + 255) / 256, 256>>>(c1, c3, c3 + (size_t)NTOK * HIDDEN, gate);

    // 9) out = h + gate @ w2^T  (64x64 tiles -> 256 CTAs)
    gemm_w2_kernel<<<dim3(64, 4), 256>>>(gate, w2, out, h, HIDDEN);
}

// round 10
// speedup vs baseline: 1.6755x; 1.0138x over previous
#include <cuda_runtime.h>
#include <cstdint>

// ---------------------------------------------------------------------------
// Problem constants
// ---------------------------------------------------------------------------
#define NTOK   256
#define DIM    4096
#define HIDDEN 14336
#define KVDIM  1024
#define NHEAD  32
#define HDIM   128
#define TSTEPS 10

typedef unsigned long long u64;

// ---------------------------------------------------------------------------
// Packed f32x2 helpers (sm_103a FFMA2 path — only reachable via PTX).
// Each lane is an independent IEEE fp32 op -> per-element bit-exactness.
// ---------------------------------------------------------------------------
__device__ __forceinline__ u64 fdup(float a) {
    u64 r; asm("mov.b64 %0, {%1, %1};" : "=l"(r) : "f"(a)); return r;
}
__device__ __forceinline__ void ffma2(u64& d, u64 a, u64 b) {
    asm("fma.rn.f32x2 %0, %1, %2, %0;" : "+l"(d) : "l"(a), "l"(b));
}
__device__ __forceinline__ void fadd2(u64& d, u64 a) {
    asm("add.rn.f32x2 %0, %0, %1;" : "+l"(d) : "l"(a));
}
__device__ __forceinline__ float2 funpack(u64 v) {
    float lo, hi; asm("mov.b64 {%0, %1}, %2;" : "=f"(lo), "=f"(hi) : "l"(v));
    return make_float2(lo, hi);
}

// ---------------------------------------------------------------------------
// Scratch (device globals)
// ---------------------------------------------------------------------------
__device__ float    g_xs [2 * NTOK * DIM];
__device__ float    g_hs [2 * NTOK * DIM];
__device__ unsigned g_qm [2 * NTOK * DIM];
__device__ unsigned g_km [2 * NTOK * KVDIM];
__device__ unsigned g_vm [2 * NTOK * KVDIM];
__device__ float    g_xat[TSTEPS * NTOK * DIM];
__device__ float    g_yt [TSTEPS * NTOK * DIM];
__device__ float    g_h  [NTOK * DIM];
__device__ float    g_c3 [2 * NTOK * HIDDEN];
__device__ float    g_c1 [NTOK * HIDDEN];
__device__ float    g_gate[NTOK * HIDDEN];

// ---------------------------------------------------------------------------
// RMSNorm + stacked relu (bit-frozen)
// ---------------------------------------------------------------------------
__global__ __launch_bounds__(1024)
void rmsnorm_relu_kernel(const float* __restrict__ x,
                         const float* __restrict__ w,
                         float* __restrict__ out)
{
    const int n = blockIdx.x;
    const int t = threadIdx.x;
    const float* xr = x + (size_t)n * DIM;

    float acc = 0.f;
    #pragma unroll
    for (int i = 0; i < 2; i++) {
        float2 v = *(const float2*)(xr + 2 * t + i * 2048);
        acc += v.x * v.x;
        acc += v.y * v.y;
    }
    #pragma unroll
    for (int o = 16; o > 0; o >>= 1)
        acc += __shfl_down_sync(0xffffffffu, acc, o);

    __shared__ float sw[32];
    __shared__ float sres;
    const int lane = t & 31, wid = t >> 5;
    if (lane == 0) sw[wid] = acc;
    __syncthreads();
    if (wid == 0) {
        float v = sw[lane];
        #pragma unroll
        for (int o = 16; o > 0; o >>= 1)
            v += __shfl_down_sync(0xffffffffu, v, o);
        if (lane == 0) sres = v;
    }
    __syncthreads();

    const float rs = rsqrtf(sres * (1.0f / 4096.0f) + 1e-5f);
    #pragma unroll
    for (int i = 0; i < 4; i++) {
        const int c = t + i * 1024;
        float v = xr[c] * rs * w[c];
        out[(size_t)n * DIM + c]          = fmaxf(v, 0.f);
        out[(size_t)(n + NTOK) * DIM + c] = fmaxf(-v, 0.f);
    }
}

// ---------------------------------------------------------------------------
// QKV GEMM: split-K=4 emulation, FFMA2 inner loop.
// k-order per output element IDENTICAL to R7 (sequential, fold @ k%1024==0).
// Tile 128x64, BK=16, 8x4/thread, 256 threads, double-buffered.
// ---------------------------------------------------------------------------
#define QBM 128
#define QBN 64
#define QBK 16
#define SPLITK_CHUNK 1024

__global__ __launch_bounds__(256, 2)
void gemm_qkv_kernel(const float* __restrict__ A,
                     const float* __restrict__ B0,
                     const float* __restrict__ B1,
                     const float* __restrict__ B2,
                     unsigned* __restrict__ C0, unsigned* __restrict__ C1,
                     unsigned* __restrict__ C2, int K)
{
    __shared__ float As[2][QBK][QBM];
    __shared__ float Bs[2][QBK][QBN];

    const int bx = blockIdx.x, by = blockIdx.y;
    const float* B; unsigned* C; int N, bxl;
    const int row0 = by * QBM;
    if (bx < 64)      { B = B0; C = C0; N = DIM;   bxl = bx; }
    else if (bx < 80) { B = B1; C = C1; N = KVDIM; bxl = bx - 64; }
    else              { B = B2; C = C2; N = KVDIM; bxl = bx - 80; }

    const int tid = threadIdx.x;
    const int tx = tid & 15;
    const int ty = tid >> 4;

    const int lrowA = tid >> 1;
    const int lcolA = (tid & 1) * 8;
    const int lrowB = tid >> 2;
    const int lcolB = (tid & 3) * 4;

    const float* Aptr = A + (size_t)(row0 + lrowA) * K + lcolA;
    const float* Bptr = B + (size_t)(bxl * QBN + lrowB) * K + lcolB;

    u64 acc2[8][2], tot2[8][2];
    #pragma unroll
    for (int i = 0; i < 8; i++)
        #pragma unroll
        for (int j = 0; j < 2; j++) { acc2[i][j] = 0ULL; tot2[i][j] = 0ULL; }

    float4 a0s, a1s, b0s;
    #define QLOAD()                                                            \
        do {                                                                   \
            a0s = *(const float4*)Aptr;                                        \
            a1s = *(const float4*)(Aptr + 4);                                  \
            b0s = *(const float4*)Bptr;                                        \
            Aptr += QBK; Bptr += QBK;                                          \
        } while (0)
    #define QSTORE(BUF)                                                        \
        do {                                                                   \
            As[BUF][lcolA + 0][lrowA] = a0s.x; As[BUF][lcolA + 1][lrowA] = a0s.y; \
            As[BUF][lcolA + 2][lrowA] = a0s.z; As[BUF][lcolA + 3][lrowA] = a0s.w; \
            As[BUF][lcolA + 4][lrowA] = a1s.x; As[BUF][lcolA + 5][lrowA] = a1s.y; \
            As[BUF][lcolA + 6][lrowA] = a1s.z; As[BUF][lcolA + 7][lrowA] = a1s.w; \
            Bs[BUF][lcolB + 0][lrowB] = b0s.x; Bs[BUF][lcolB + 1][lrowB] = b0s.y; \
            Bs[BUF][lcolB + 2][lrowB] = b0s.z; Bs[BUF][lcolB + 3][lrowB] = b0s.w; \
        } while (0)

    QLOAD(); QSTORE(0);
    __syncthreads();

    int buf = 0;
    for (int k0 = 0; k0 < K; k0 += QBK) {
        const bool has_next = (k0 + QBK < K);
        if (has_next) QLOAD();

        #pragma unroll
        for (int kk = 0; kk < QBK; kk++) {
            float4 a0 = *(const float4*)&As[buf][kk][ty * 8];
            float4 a1 = *(const float4*)&As[buf][kk][ty * 8 + 4];
            ulonglong2 bp = *(const ulonglong2*)&Bs[buf][kk][tx * 4];
            u64 b_pk[2] = { bp.x, bp.y };
            u64 a_pk[8] = { fdup(a0.x), fdup(a0.y), fdup(a0.z), fdup(a0.w),
                            fdup(a1.x), fdup(a1.y), fdup(a1.z), fdup(a1.w) };
            #pragma unroll
            for (int i = 0; i < 8; i++)
                #pragma unroll
                for (int jp = 0; jp < 2; jp++)
                    ffma2(acc2[i][jp], a_pk[i], b_pk[jp]);
        }

        if (((k0 + QBK) & (SPLITK_CHUNK - 1)) == 0) {
            #pragma unroll
            for (int i = 0; i < 8; i++)
                #pragma unroll
                for (int jp = 0; jp < 2; jp++) {
                    fadd2(tot2[i][jp], acc2[i][jp]);   // per-lane add.rn == FADD
                    acc2[i][jp] = 0ULL;
                }
        }

        if (has_next) QSTORE(buf ^ 1);
        __syncthreads();
        buf ^= 1;
    }
    #undef QLOAD
    #undef QSTORE

    #pragma unroll
    for (int i = 0; i < 8; i++) {
        const int r = row0 + ty * 8 + i;
        #pragma unroll
        for (int jp = 0; jp < 2; jp++) {
            float2 yv = funpack(tot2[i][jp]);
            #pragma unroll
            for (int l = 0; l < 2; l++) {
                const int col = bxl * QBN + tx * 4 + jp * 2 + l;
                float y = (l == 0) ? yv.x : yv.y;
                unsigned m = 0; float vm = 0.f;
                #pragma unroll
                for (int t = 0; t < TSTEPS; t++) {
                    vm += y;
                    if (vm - 1.0f >= 0.f) { m |= (1u << t); vm = 0.f; }
                }
                C[(size_t)r * N + col] = m;
            }
        }
    }
}

// ---------------------------------------------------------------------------
// Big GEMM (NT), 128x128 tile, 8x8/thread, BK=16, double-buffered, FFMA2.
//   MODE 1: FFN spike counts (N=HIDDEN; by<4 -> w3/c3 M=512; else w1/c1 M=256)
//   MODE 2: plain f32 store (per-t wo GEMM, M=2560, N=DIM)
// ---------------------------------------------------------------------------
#define BM2 128
#define BN2 128
#define BK2 16

template<int MODE>
__global__ __launch_bounds__(256, 2)
void gemm2_kernel(const float* __restrict__ A,
                  const float* __restrict__ B0,
                  const float* __restrict__ B1,
                  void* __restrict__ C0, void* __restrict__ C1, int K)
{
    __shared__ float As[2][BK2][BM2];
    __shared__ float Bs[2][BK2][BN2];

    const int bx = blockIdx.x, by = blockIdx.y;
    const float* B; void* C; int N, row0;
    if (MODE == 1) {
        N = HIDDEN;
        if (by < 4) { B = B0; C = C0; row0 = by * BM2; }
        else        { B = B1; C = C1; row0 = (by - 4) * BM2; }
    } else {
        N = DIM; B = B0; C = C0; row0 = by * BM2;
    }

    const int tid = threadIdx.x;
    const int tx = tid & 15;
    const int ty = tid >> 4;
    const int lrow = tid >> 1;
    const int lcol = (tid & 1) * 8;

    const float* Aptr = A + (size_t)(row0 + lrow) * K + lcol;
    const float* Bptr = B + (size_t)(bx * BN2 + lrow) * K + lcol;

    u64 acc2[8][4];
    #pragma unroll
    for (int i = 0; i < 8; i++)
        #pragma unroll
        for (int jp = 0; jp < 4; jp++) acc2[i][jp] = 0ULL;

    float4 a0s, a1s, b0s, b1s;
    #define GLOAD()                                                            \
        do {                                                                   \
            a0s = *(const float4*)Aptr;                                        \
            a1s = *(const float4*)(Aptr + 4);                                  \
            b0s = *(const float4*)Bptr;                                        \
            b1s = *(const float4*)(Bptr + 4);                                  \
            Aptr += BK2; Bptr += BK2;                                          \
        } while (0)
    #define GSTORE(BUF)                                                        \
        do {                                                                   \
            As[BUF][lcol + 0][lrow] = a0s.x; As[BUF][lcol + 1][lrow] = a0s.y;  \
            As[BUF][lcol + 2][lrow] = a0s.z; As[BUF][lcol + 3][lrow] = a0s.w;  \
            As[BUF][lcol + 4][lrow] = a1s.x; As[BUF][lcol + 5][lrow] = a1s.y;  \
            As[BUF][lcol + 6][lrow] = a1s.z; As[BUF][lcol + 7][lrow] = a1s.w;  \
            Bs[BUF][lcol + 0][lrow] = b0s.x; Bs[BUF][lcol + 1][lrow] = b0s.y;  \
            Bs[BUF][lcol + 2][lrow] = b0s.z; Bs[BUF][lcol + 3][lrow] = b0s.w;  \
            Bs[BUF][lcol + 4][lrow] = b1s.x; Bs[BUF][lcol + 5][lrow] = b1s.y;  \
            Bs[BUF][lcol + 6][lrow] = b1s.z; Bs[BUF][lcol + 7][lrow] = b1s.w;  \
        } while (0)

    GLOAD(); GSTORE(0);
    __syncthreads();

    int buf = 0;
    for (int k0 = 0; k0 < K; k0 += BK2) {
        const bool has_next = (k0 + BK2 < K);
        if (has_next) GLOAD();

        #pragma unroll
        for (int kk = 0; kk < BK2; kk++) {
            float4 a0 = *(const float4*)&As[buf][kk][ty * 8];
            float4 a1 = *(const float4*)&As[buf][kk][ty * 8 + 4];
            ulonglong2 bp0 = *(const ulonglong2*)&Bs[buf][kk][tx * 8];
            ulonglong2 bp1 = *(const ulonglong2*)&Bs[buf][kk][tx * 8 + 4];
            u64 b_pk[4] = { bp0.x, bp0.y, bp1.x, bp1.y };
            u64 a_pk[8] = { fdup(a0.x), fdup(a0.y), fdup(a0.z), fdup(a0.w),
                            fdup(a1.x), fdup(a1.y), fdup(a1.z), fdup(a1.w) };
            #pragma unroll
            for (int i = 0; i < 8; i++)
                #pragma unroll
                for (int jp = 0; jp < 4; jp++)
                    ffma2(acc2[i][jp], a_pk[i], b_pk[jp]);
        }

        if (has_next) GSTORE(buf ^ 1);
        __syncthreads();
        buf ^= 1;
    }
    #undef GLOAD
    #undef GSTORE

    #pragma unroll
    for (int i = 0; i < 8; i++) {
        const int r = row0 + ty * 8 + i;
        #pragma unroll
        for (int jp = 0; jp < 4; jp++) {
            float2 yv = funpack(acc2[i][jp]);
            #pragma unroll
            for (int l = 0; l < 2; l++) {
                const int col = bx * BN2 + tx * 8 + jp * 2 + l;
                const size_t idx = (size_t)r * N + col;
                float y = (l == 0) ? yv.x : yv.y;
                if (MODE == 1) {
                    int cnt = 0; float vm = 0.f;
                    #pragma unroll
                    for (int t = 0; t < TSTEPS; t++) {
                        vm += y;
                        if (vm - 1.0f >= 0.f) { cnt++; vm = 0.f; }
                    }
                    ((float*)C)[idx] = (float)cnt;
                } else {
                    ((float*)C)[idx] = y;
                }
            }
        }
    }
}

// ---------------------------------------------------------------------------
// w2 GEMM: 64x64 tile (256 CTAs), BK=32, 4x4/thread, FFMA2.
// ---------------------------------------------------------------------------
#define WBM 64
#define WBN 64
#define WBK 32

__global__ __launch_bounds__(256)
void gemm_w2_kernel(const float* __restrict__ A,
                    const float* __restrict__ B,
                    float* __restrict__ C,
                    const float* __restrict__ addv, int K)
{
    __shared__ float As[2][WBK][WBM];
    __shared__ float Bs[2][WBK][WBN];

    const int bx = blockIdx.x, by = blockIdx.y;
    const int row0 = by * WBM;
    const int tid = threadIdx.x;
    const int tx = tid & 15;
    const int ty = tid >> 4;
    const int lrow = tid >> 2;
    const int lcol = (tid & 3) * 8;

    const float* Aptr = A + (size_t)(row0 + lrow) * K + lcol;
    const float* Bptr = B + (size_t)(bx * WBN + lrow) * K + lcol;

    u64 acc2[4][2];
    #pragma unroll
    for (int i = 0; i < 4; i++)
        #pragma unroll
        for (int jp = 0; jp < 2; jp++) acc2[i][jp] = 0ULL;

    float4 a0s, a1s, b0s, b1s;
    #define WLOAD()                                                            \
        do {                                                                   \
            a0s = *(const float4*)Aptr;                                        \
            a1s = *(const float4*)(Aptr + 4);                                  \
            b0s = *(const float4*)Bptr;                                        \
            b1s = *(const float4*)(Bptr + 4);                                  \
            Aptr += WBK; Bptr += WBK;                                          \
        } while (0)
    #define WSTORE(BUF)                                                        \
        do {                                                                   \
            As[BUF][lcol + 0][lrow] = a0s.x; As[BUF][lcol + 1][lrow] = a0s.y;  \
            As[BUF][lcol + 2][lrow] = a0s.z; As[BUF][lcol + 3][lrow] = a0s.w;  \
            As[BUF][lcol + 4][lrow] = a1s.x; As[BUF][lcol + 5][lrow] = a1s.y;  \
            As[BUF][lcol + 6][lrow] = a1s.z; As[BUF][lcol + 7][lrow] = a1s.w;  \
            Bs[BUF][lcol + 0][lrow] = b0s.x; Bs[BUF][lcol + 1][lrow] = b0s.y;  \
            Bs[BUF][lcol + 2][lrow] = b0s.z; Bs[BUF][lcol + 3][lrow] = b0s.w;  \
            Bs[BUF][lcol + 4][lrow] = b1s.x; Bs[BUF][lcol + 5][lrow] = b1s.y;  \
            Bs[BUF][lcol + 6][lrow] = b1s.z; Bs[BUF][lcol + 7][lrow] = b1s.w;  \
        } while (0)

    WLOAD(); WSTORE(0);
    __syncthreads();

    int buf = 0;
    for (int k0 = 0; k0 < K; k0 += WBK) {
        const bool has_next = (k0 + WBK < K);
        if (has_next) WLOAD();

        #pragma unroll
        for (int kk = 0; kk < WBK; kk++) {
            float4 a0 = *(const float4*)&As[buf][kk][ty * 4];
            ulonglong2 bp = *(const ulonglong2*)&Bs[buf][kk][tx * 4];
            u64 b_pk[2] = { bp.x, bp.y };
            u64 a_pk[4] = { fdup(a0.x), fdup(a0.y), fdup(a0.z), fdup(a0.w) };
            #pragma unroll
            for (int i = 0; i < 4; i++)
                #pragma unroll
                for (int jp = 0; jp < 2; jp++)
                    ffma2(acc2[i][jp], a_pk[i], b_pk[jp]);
        }

        if (has_next) WSTORE(buf ^ 1);
        __syncthreads();
        buf ^= 1;
    }
    #undef WLOAD
    #undef WSTORE

    #pragma unroll
    for (int i = 0; i < 4; i++) {
        const int r = row0 + ty * 4 + i;
        #pragma unroll
        for (int jp = 0; jp < 2; jp++) {
            float2 yv = funpack(acc2[i][jp]);
            #pragma unroll
            for (int l = 0; l < 2; l++) {
                const int col = bx * WBN + tx * 4 + jp * 2 + l;
                const size_t idx = (size_t)r * DIM + col;
                C[idx] = addv[idx] + ((l == 0) ? yv.x : yv.y);
            }
        }
    }
}

// ---------------------------------------------------------------------------
// gate = (c1/10) * ((c3p - c3n)/10)
// ---------------------------------------------------------------------------
__global__ void gate_kernel(const float* __restrict__ c1,
                            const float* __restrict__ c3p,
                            const float* __restrict__ c3n,
                            float* __restrict__ g)
{
    const int i = blockIdx.x * blockDim.x + threadIdx.x;
    if (i < NTOK * HIDDEN)
        g[i] = (c1[i] / 10.0f) * ((c3p[i] - c3n[i]) / 10.0f);
}

// ---------------------------------------------------------------------------
// Spike attention (bit-frozen)
// ---------------------------------------------------------------------------
__global__ void attn_kernel(const unsigned* __restrict__ qm,
                            const unsigned* __restrict__ km,
                            const unsigned* __restrict__ vm,
                            float* __restrict__ xat)
{
    __shared__ unsigned sq[128 * 33];
    __shared__ unsigned sk[128 * 9];
    __shared__ unsigned sv[8 * 128];
    __shared__ int      S[NHEAD * 8];

    const int n   = blockIdx.x;
    const int tid = threadIdx.x;

    for (int idx = tid; idx < NHEAD * HDIM; idx += 128) {
        const int i = idx >> 7, d = idx & 127;
        sq[d * 33 + i] = qm[(size_t)n * DIM + idx] | (qm[(size_t)(n + NTOK) * DIM + idx] << 16);
    }
    for (int idx = tid; idx < 8 * HDIM; idx += 128) {
        const int j = idx >> 7, d = idx & 127;
        sk[d * 9 + j] = km[(size_t)n * KVDIM + idx] | (km[(size_t)(n + NTOK) * KVDIM + idx] << 16);
        sv[idx]       = vm[(size_t)n * KVDIM + idx] | (vm[(size_t)(n + NTOK) * KVDIM + idx] << 16);
    }
    __syncthreads();

    for (int t = 0; t < TSTEPS; t++) {
        #pragma unroll
        for (int e0 = 0; e0 < 2; e0++) {
            const int e = tid + e0 * 128;
            const int i = e >> 3, j = e & 7;
            int s = 0;
            for (int d2 = 0; d2 < HDIM; d2++) {
                const unsigned q = sq[d2 * 33 + i];
                const unsigned k = sk[d2 * 9 + j];
                const int qv = (int)((q >> t) & 1u) - (int)((q >> (t + 16)) & 1u);
                const int kv = (int)((k >> t) & 1u) - (int)((k >> (t + 16)) & 1u);
                s += qv * kv;
            }
            S[e] = s;
        }
        __syncthreads();

        {
            const int d2 = tid;
            int vv[8];
            #pragma unroll
            for (int j = 0; j < 8; j++) {
                const unsigned v = sv[j * 128 + d2];
                vv[j] = (int)((v >> t) & 1u) - (int)((v >> (t + 16)) & 1u);
            }
            float* orow = xat + ((size_t)t * NTOK + n) * DIM + (size_t)d2 * NHEAD;
            #pragma unroll
            for (int i = 0; i < NHEAD; i++) {
                int s = 0;
                #pragma unroll
                for (int j = 0; j < 8; j++) s += S[i * 8 + j] * vv[j];
                orow[i] = (float)s * 0.5f;
            }
        }
        __syncthreads();
    }
}

// ---------------------------------------------------------------------------
// h = x + mean_t(y_t) (bit-frozen)
// ---------------------------------------------------------------------------
__global__ void wo_mean_kernel(const float* __restrict__ yt,
                               const float* __restrict__ x,
                               float* __restrict__ h)
{
    const int idx = blockIdx.x * blockDim.x + threadIdx.x;
    if (idx >= NTOK * DIM) return;
    float s = 0.f;
    #pragma unroll
    for (int t = 0; t < TSTEPS; t++)
        s += yt[(size_t)t * NTOK * DIM + idx];
    h[idx] = x[idx] + s / 10.0f;
}

// ---------------------------------------------------------------------------
// Launch
// ---------------------------------------------------------------------------
extern "C" void kernel_launch(void* const* d_in, const int* in_sizes, int n_in,
                              void* d_out, int out_size)
{
    const float* x           = (const float*)d_in[0];
    const float* attn_norm_w = (const float*)d_in[2];
    const float* ffn_norm_w  = (const float*)d_in[3];
    const float* wq          = (const float*)d_in[4];
    const float* wk          = (const float*)d_in[5];
    const float* wv          = (const float*)d_in[6];
    const float* wo          = (const float*)d_in[7];
    const float* w1          = (const float*)d_in[8];
    const float* w2          = (const float*)d_in[9];
    const float* w3          = (const float*)d_in[10];
    float* out = (float*)d_out;

    float *xs, *hs, *xat, *yt, *h, *c3, *c1, *gate;
    unsigned *qm, *km, *vm;
    cudaGetSymbolAddress((void**)&xs,   g_xs);
    cudaGetSymbolAddress((void**)&hs,   g_hs);
    cudaGetSymbolAddress((void**)&qm,   g_qm);
    cudaGetSymbolAddress((void**)&km,   g_km);
    cudaGetSymbolAddress((void**)&vm,   g_vm);
    cudaGetSymbolAddress((void**)&xat,  g_xat);
    cudaGetSymbolAddress((void**)&yt,   g_yt);
    cudaGetSymbolAddress((void**)&h,    g_h);
    cudaGetSymbolAddress((void**)&c3,   g_c3);
    cudaGetSymbolAddress((void**)&c1,   g_c1);
    cudaGetSymbolAddress((void**)&gate, g_gate);

    // 1) attn rmsnorm + stacked relu
    rmsnorm_relu_kernel<<<NTOK, 1024>>>(x, attn_norm_w, xs);

    // 2) fused QKV spike-mask projections (split-K=4, FFMA2)
    gemm_qkv_kernel<<<dim3(96, 4), 256>>>(xs, wq, wk, wv, qm, km, vm, DIM);

    // 3) exact spike attention -> per-timestep planes
    attn_kernel<<<NTOK, 128>>>(qm, km, vm, xat);

    // 4) per-t wo GEMM: yt = xat @ wo^T  (M=2560, FFMA2)
    gemm2_kernel<2><<<dim3(32, 20), 256>>>(xat, wo, nullptr, yt, nullptr, DIM);

    // 5) h = x + mean_t(y_t)
    wo_mean_kernel<<<(NTOK * DIM + 255) / 256, 256>>>(yt, x, h);

    // 6) ffn rmsnorm + stacked relu
    rmsnorm_relu_kernel<<<NTOK, 1024>>>(h, ffn_norm_w, hs);

    // 7) fused FFN spike-count projections: w3 (M=512) + w1 (M=256), FFMA2
    gemm2_kernel<1><<<dim3(112, 6), 256>>>(hs, w3, w1, c3, c1, DIM);

    // 8) gate (elementwise)
    gate_kernel<<<(NTOK * HIDDEN + 255) / 256, 256>>>(c1, c3, c3 + (size_t)NTOK * HIDDEN, gate);

    // 9) out = h + gate @ w2^T  (FFMA2)
    gemm_w2_kernel<<<dim3(64, 4), 256>>>(gate, w2, out, h, HIDDEN);
}

// round 11
// speedup vs baseline: 1.8981x; 1.1329x over previous
#include <cuda_runtime.h>
#include <cstdint>

// ---------------------------------------------------------------------------
// Problem constants
// ---------------------------------------------------------------------------
#define NTOK   256
#define DIM    4096
#define HIDDEN 14336
#define KVDIM  1024
#define NHEAD  32
#define HDIM   128
#define TSTEPS 10

typedef unsigned long long u64;

// ---------------------------------------------------------------------------
// Packed f32x2 helpers (sm_103a FFMA2 path — only reachable via PTX).
// Each lane is an independent IEEE fp32 op -> per-element bit-exactness.
// ---------------------------------------------------------------------------
__device__ __forceinline__ u64 fdup(float a) {
    u64 r; asm("mov.b64 %0, {%1, %1};" : "=l"(r) : "f"(a)); return r;
}
__device__ __forceinline__ void ffma2(u64& d, u64 a, u64 b) {
    asm("fma.rn.f32x2 %0, %1, %2, %0;" : "+l"(d) : "l"(a), "l"(b));
}
__device__ __forceinline__ void fadd2(u64& d, u64 a) {
    asm("add.rn.f32x2 %0, %0, %1;" : "+l"(d) : "l"(a));
}
__device__ __forceinline__ float2 funpack(u64 v) {
    float lo, hi; asm("mov.b64 {%0, %1}, %2;" : "=f"(lo), "=f"(hi) : "l"(v));
    return make_float2(lo, hi);
}

// ---------------------------------------------------------------------------
// Scratch (device globals)
// ---------------------------------------------------------------------------
__device__ float    g_xs [2 * NTOK * DIM];
__device__ float    g_hs [2 * NTOK * DIM];
__device__ unsigned g_qm [2 * NTOK * DIM];
__device__ unsigned g_km [2 * NTOK * KVDIM];
__device__ unsigned g_vm [2 * NTOK * KVDIM];
__device__ float    g_xat[TSTEPS * NTOK * DIM];
__device__ float    g_yt [TSTEPS * NTOK * DIM];
__device__ float    g_h  [NTOK * DIM];
__device__ float    g_c3 [2 * NTOK * HIDDEN];
__device__ float    g_c1 [NTOK * HIDDEN];
__device__ float    g_gate[NTOK * HIDDEN];

// ---------------------------------------------------------------------------
// RMSNorm + stacked relu (bit-frozen)
// ---------------------------------------------------------------------------
__global__ __launch_bounds__(1024)
void rmsnorm_relu_kernel(const float* __restrict__ x,
                         const float* __restrict__ w,
                         float* __restrict__ out)
{
    const int n = blockIdx.x;
    const int t = threadIdx.x;
    const float* xr = x + (size_t)n * DIM;

    float acc = 0.f;
    #pragma unroll
    for (int i = 0; i < 2; i++) {
        float2 v = *(const float2*)(xr + 2 * t + i * 2048);
        acc += v.x * v.x;
        acc += v.y * v.y;
    }
    #pragma unroll
    for (int o = 16; o > 0; o >>= 1)
        acc += __shfl_down_sync(0xffffffffu, acc, o);

    __shared__ float sw[32];
    __shared__ float sres;
    const int lane = t & 31, wid = t >> 5;
    if (lane == 0) sw[wid] = acc;
    __syncthreads();
    if (wid == 0) {
        float v = sw[lane];
        #pragma unroll
        for (int o = 16; o > 0; o >>= 1)
            v += __shfl_down_sync(0xffffffffu, v, o);
        if (lane == 0) sres = v;
    }
    __syncthreads();

    const float rs = rsqrtf(sres * (1.0f / 4096.0f) + 1e-5f);
    #pragma unroll
    for (int i = 0; i < 4; i++) {
        const int c = t + i * 1024;
        float v = xr[c] * rs * w[c];
        out[(size_t)n * DIM + c]          = fmaxf(v, 0.f);
        out[(size_t)(n + NTOK) * DIM + c] = fmaxf(-v, 0.f);
    }
}

// ---------------------------------------------------------------------------
// QKV GEMM: split-K=4 emulation, FFMA2 (bit-frozen numerics).
// ---------------------------------------------------------------------------
#define QBM 128
#define QBN 64
#define QBK 16
#define SPLITK_CHUNK 1024

__global__ __launch_bounds__(256, 2)
void gemm_qkv_kernel(const float* __restrict__ A,
                     const float* __restrict__ B0,
                     const float* __restrict__ B1,
                     const float* __restrict__ B2,
                     unsigned* __restrict__ C0, unsigned* __restrict__ C1,
                     unsigned* __restrict__ C2, int K)
{
    __shared__ float As[2][QBK][QBM];
    __shared__ float Bs[2][QBK][QBN];

    const int bx = blockIdx.x, by = blockIdx.y;
    const float* B; unsigned* C; int N, bxl;
    const int row0 = by * QBM;
    if (bx < 64)      { B = B0; C = C0; N = DIM;   bxl = bx; }
    else if (bx < 80) { B = B1; C = C1; N = KVDIM; bxl = bx - 64; }
    else              { B = B2; C = C2; N = KVDIM; bxl = bx - 80; }

    const int tid = threadIdx.x;
    const int tx = tid & 15;
    const int ty = tid >> 4;

    const int lrowA = tid >> 1;
    const int lcolA = (tid & 1) * 8;
    const int lrowB = tid >> 2;
    const int lcolB = (tid & 3) * 4;

    const float* Aptr = A + (size_t)(row0 + lrowA) * K + lcolA;
    const float* Bptr = B + (size_t)(bxl * QBN + lrowB) * K + lcolB;

    u64 acc2[8][2], tot2[8][2];
    #pragma unroll
    for (int i = 0; i < 8; i++)
        #pragma unroll
        for (int j = 0; j < 2; j++) { acc2[i][j] = 0ULL; tot2[i][j] = 0ULL; }

    float4 a0s, a1s, b0s;
    #define QLOAD()                                                            \
        do {                                                                   \
            a0s = *(const float4*)Aptr;                                        \
            a1s = *(const float4*)(Aptr + 4);                                  \
            b0s = *(const float4*)Bptr;                                        \
            Aptr += QBK; Bptr += QBK;                                          \
        } while (0)
    #define QSTORE(BUF)                                                        \
        do {                                                                   \
            As[BUF][lcolA + 0][lrowA] = a0s.x; As[BUF][lcolA + 1][lrowA] = a0s.y; \
            As[BUF][lcolA + 2][lrowA] = a0s.z; As[BUF][lcolA + 3][lrowA] = a0s.w; \
            As[BUF][lcolA + 4][lrowA] = a1s.x; As[BUF][lcolA + 5][lrowA] = a1s.y; \
            As[BUF][lcolA + 6][lrowA] = a1s.z; As[BUF][lcolA + 7][lrowA] = a1s.w; \
            Bs[BUF][lcolB + 0][lrowB] = b0s.x; Bs[BUF][lcolB + 1][lrowB] = b0s.y; \
            Bs[BUF][lcolB + 2][lrowB] = b0s.z; Bs[BUF][lcolB + 3][lrowB] = b0s.w; \
        } while (0)

    QLOAD(); QSTORE(0);
    __syncthreads();

    int buf = 0;
    for (int k0 = 0; k0 < K; k0 += QBK) {
        const bool has_next = (k0 + QBK < K);
        if (has_next) QLOAD();

        #pragma unroll
        for (int kk = 0; kk < QBK; kk++) {
            float4 a0 = *(const float4*)&As[buf][kk][ty * 8];
            float4 a1 = *(const float4*)&As[buf][kk][ty * 8 + 4];
            ulonglong2 bp = *(const ulonglong2*)&Bs[buf][kk][tx * 4];
            u64 b_pk[2] = { bp.x, bp.y };
            u64 a_pk[8] = { fdup(a0.x), fdup(a0.y), fdup(a0.z), fdup(a0.w),
                            fdup(a1.x), fdup(a1.y), fdup(a1.z), fdup(a1.w) };
            #pragma unroll
            for (int i = 0; i < 8; i++)
                #pragma unroll
                for (int jp = 0; jp < 2; jp++)
                    ffma2(acc2[i][jp], a_pk[i], b_pk[jp]);
        }

        if (((k0 + QBK) & (SPLITK_CHUNK - 1)) == 0) {
            #pragma unroll
            for (int i = 0; i < 8; i++)
                #pragma unroll
                for (int jp = 0; jp < 2; jp++) {
                    fadd2(tot2[i][jp], acc2[i][jp]);
                    acc2[i][jp] = 0ULL;
                }
        }

        if (has_next) QSTORE(buf ^ 1);
        __syncthreads();
        buf ^= 1;
    }
    #undef QLOAD
    #undef QSTORE

    #pragma unroll
    for (int i = 0; i < 8; i++) {
        const int r = row0 + ty * 8 + i;
        #pragma unroll
        for (int jp = 0; jp < 2; jp++) {
            float2 yv = funpack(tot2[i][jp]);
            #pragma unroll
            for (int l = 0; l < 2; l++) {
                const int col = bxl * QBN + tx * 4 + jp * 2 + l;
                float y = (l == 0) ? yv.x : yv.y;
                unsigned m = 0; float vm = 0.f;
                #pragma unroll
                for (int t = 0; t < TSTEPS; t++) {
                    vm += y;
                    if (vm - 1.0f >= 0.f) { m |= (1u << t); vm = 0.f; }
                }
                C[(size_t)r * N + col] = m;
            }
        }
    }
}

// ---------------------------------------------------------------------------
// Big GEMM (NT), 128x128 tile, 8x8/thread, BK=16, double-buffered, FFMA2.
// SPLIT-FRAGMENT mapping (conflict-free LDS):
//   rows  = {ty*4..ty*4+3} u {64+ty*4..+3}
//   cols  = {tx*4..tx*4+3} u {64+tx*4..+3}
// Fragment LDS.128s sit at 16B lane stride -> 2 phases (bandwidth minimum).
// Per-element k-order identical to before (mapping change only).
// ---------------------------------------------------------------------------
#define BM2 128
#define BN2 128
#define BK2 16

template<int MODE>
__global__ __launch_bounds__(256, 2)
void gemm2_kernel(const float* __restrict__ A,
                  const float* __restrict__ B0,
                  const float* __restrict__ B1,
                  void* __restrict__ C0, void* __restrict__ C1, int K)
{
    __shared__ float As[2][BK2][BM2];
    __shared__ float Bs[2][BK2][BN2];

    const int bx = blockIdx.x, by = blockIdx.y;
    const float* B; void* C; int N, row0;
    if (MODE == 1) {
        N = HIDDEN;
        if (by < 4) { B = B0; C = C0; row0 = by * BM2; }
        else        { B = B1; C = C1; row0 = (by - 4) * BM2; }
    } else {
        N = DIM; B = B0; C = C0; row0 = by * BM2;
    }

    const int tid = threadIdx.x;
    const int tx = tid & 15;
    const int ty = tid >> 4;
    const int lrow = tid >> 1;
    const int lcol = (tid & 1) * 8;

    const float* Aptr = A + (size_t)(row0 + lrow) * K + lcol;
    const float* Bptr = B + (size_t)(bx * BN2 + lrow) * K + lcol;

    // acc2[i][jp]: i 0..3 -> row ty*4+i ; i 4..7 -> row 64+ty*4+(i-4)
    //              jp 0..1 -> cols tx*4+2jp+{0,1} ; jp 2..3 -> 64+tx*4+2(jp-2)+{0,1}
    u64 acc2[8][4];
    #pragma unroll
    for (int i = 0; i < 8; i++)
        #pragma unroll
        for (int jp = 0; jp < 4; jp++) acc2[i][jp] = 0ULL;

    float4 a0s, a1s, b0s, b1s;
    #define GLOAD()                                                            \
        do {                                                                   \
            a0s = *(const float4*)Aptr;                                        \
            a1s = *(const float4*)(Aptr + 4);                                  \
            b0s = *(const float4*)Bptr;                                        \
            b1s = *(const float4*)(Bptr + 4);                                  \
            Aptr += BK2; Bptr += BK2;                                          \
        } while (0)
    #define GSTORE(BUF)                                                        \
        do {                                                                   \
            As[BUF][lcol + 0][lrow] = a0s.x; As[BUF][lcol + 1][lrow] = a0s.y;  \
            As[BUF][lcol + 2][lrow] = a0s.z; As[BUF][lcol + 3][lrow] = a0s.w;  \
            As[BUF][lcol + 4][lrow] = a1s.x; As[BUF][lcol + 5][lrow] = a1s.y;  \
            As[BUF][lcol + 6][lrow] = a1s.z; As[BUF][lcol + 7][lrow] = a1s.w;  \
            Bs[BUF][lcol + 0][lrow] = b0s.x; Bs[BUF][lcol + 1][lrow] = b0s.y;  \
            Bs[BUF][lcol + 2][lrow] = b0s.z; Bs[BUF][lcol + 3][lrow] = b0s.w;  \
            Bs[BUF][lcol + 4][lrow] = b1s.x; Bs[BUF][lcol + 5][lrow] = b1s.y;  \
            Bs[BUF][lcol + 6][lrow] = b1s.z; Bs[BUF][lcol + 7][lrow] = b1s.w;  \
        } while (0)

    GLOAD(); GSTORE(0);
    __syncthreads();

    int buf = 0;
    for (int k0 = 0; k0 < K; k0 += BK2) {
        const bool has_next = (k0 + BK2 < K);
        if (has_next) GLOAD();

        #pragma unroll
        for (int kk = 0; kk < BK2; kk++) {
            // conflict-free fragment loads: 16B lane stride, 256B span
            float4 a0 = *(const float4*)&As[buf][kk][ty * 4];
            float4 a1 = *(const float4*)&As[buf][kk][64 + ty * 4];
            ulonglong2 bp0 = *(const ulonglong2*)&Bs[buf][kk][tx * 4];
            ulonglong2 bp1 = *(const ulonglong2*)&Bs[buf][kk][64 + tx * 4];
            u64 b_pk[4] = { bp0.x, bp0.y, bp1.x, bp1.y };
            u64 a_pk[8] = { fdup(a0.x), fdup(a0.y), fdup(a0.z), fdup(a0.w),
                            fdup(a1.x), fdup(a1.y), fdup(a1.z), fdup(a1.w) };
            #pragma unroll
            for (int i = 0; i < 8; i++)
                #pragma unroll
                for (int jp = 0; jp < 4; jp++)
                    ffma2(acc2[i][jp], a_pk[i], b_pk[jp]);
        }

        if (has_next) GSTORE(buf ^ 1);
        __syncthreads();
        buf ^= 1;
    }
    #undef GLOAD
    #undef GSTORE

    #pragma unroll
    for (int i = 0; i < 8; i++) {
        const int r = row0 + ((i < 4) ? (ty * 4 + i) : (64 + ty * 4 + (i - 4)));
        #pragma unroll
        for (int jp = 0; jp < 4; jp++) {
            const int colbase = bx * BN2 +
                ((jp < 2) ? (tx * 4 + jp * 2) : (64 + tx * 4 + (jp - 2) * 2));
            float2 yv = funpack(acc2[i][jp]);
            #pragma unroll
            for (int l = 0; l < 2; l++) {
                const size_t idx = (size_t)r * N + colbase + l;
                float y = (l == 0) ? yv.x : yv.y;
                if (MODE == 1) {
                    int cnt = 0; float vm = 0.f;
                    #pragma unroll
                    for (int t = 0; t < TSTEPS; t++) {
                        vm += y;
                        if (vm - 1.0f >= 0.f) { cnt++; vm = 0.f; }
                    }
                    ((float*)C)[idx] = (float)cnt;
                } else {
                    ((float*)C)[idx] = y;
                }
            }
        }
    }
}

// ---------------------------------------------------------------------------
// w2 GEMM: 64x64 tile (256 CTAs), BK=32, 4x4/thread, FFMA2.
// ---------------------------------------------------------------------------
#define WBM 64
#define WBN 64
#define WBK 32

__global__ __launch_bounds__(256)
void gemm_w2_kernel(const float* __restrict__ A,
                    const float* __restrict__ B,
                    float* __restrict__ C,
                    const float* __restrict__ addv, int K)
{
    __shared__ float As[2][WBK][WBM];
    __shared__ float Bs[2][WBK][WBN];

    const int bx = blockIdx.x, by = blockIdx.y;
    const int row0 = by * WBM;
    const int tid = threadIdx.x;
    const int tx = tid & 15;
    const int ty = tid >> 4;
    const int lrow = tid >> 2;
    const int lcol = (tid & 3) * 8;

    const float* Aptr = A + (size_t)(row0 + lrow) * K + lcol;
    const float* Bptr = B + (size_t)(bx * WBN + lrow) * K + lcol;

    u64 acc2[4][2];
    #pragma unroll
    for (int i = 0; i < 4; i++)
        #pragma unroll
        for (int jp = 0; jp < 2; jp++) acc2[i][jp] = 0ULL;

    float4 a0s, a1s, b0s, b1s;
    #define WLOAD()                                                            \
        do {                                                                   \
            a0s = *(const float4*)Aptr;                                        \
            a1s = *(const float4*)(Aptr + 4);                                  \
            b0s = *(const float4*)Bptr;                                        \
            b1s = *(const float4*)(Bptr + 4);                                  \
            Aptr += WBK; Bptr += WBK;                                          \
        } while (0)
    #define WSTORE(BUF)                                                        \
        do {                                                                   \
            As[BUF][lcol + 0][lrow] = a0s.x; As[BUF][lcol + 1][lrow] = a0s.y;  \
            As[BUF][lcol + 2][lrow] = a0s.z; As[BUF][lcol + 3][lrow] = a0s.w;  \
            As[BUF][lcol + 4][lrow] = a1s.x; As[BUF][lcol + 5][lrow] = a1s.y;  \
            As[BUF][lcol + 6][lrow] = a1s.z; As[BUF][lcol + 7][lrow] = a1s.w;  \
            Bs[BUF][lcol + 0][lrow] = b0s.x; Bs[BUF][lcol + 1][lrow] = b0s.y;  \
            Bs[BUF][lcol + 2][lrow] = b0s.z; Bs[BUF][lcol + 3][lrow] = b0s.w;  \
            Bs[BUF][lcol + 4][lrow] = b1s.x; Bs[BUF][lcol + 5][lrow] = b1s.y;  \
            Bs[BUF][lcol + 6][lrow] = b1s.z; Bs[BUF][lcol + 7][lrow] = b1s.w;  \
        } while (0)

    WLOAD(); WSTORE(0);
    __syncthreads();

    int buf = 0;
    for (int k0 = 0; k0 < K; k0 += WBK) {
        const bool has_next = (k0 + WBK < K);
        if (has_next) WLOAD();

        #pragma unroll
        for (int kk = 0; kk < WBK; kk++) {
            float4 a0 = *(const float4*)&As[buf][kk][ty * 4];
            ulonglong2 bp = *(const ulonglong2*)&Bs[buf][kk][tx * 4];
            u64 b_pk[2] = { bp.x, bp.y };
            u64 a_pk[4] = { fdup(a0.x), fdup(a0.y), fdup(a0.z), fdup(a0.w) };
            #pragma unroll
            for (int i = 0; i < 4; i++)
                #pragma unroll
                for (int jp = 0; jp < 2; jp++)
                    ffma2(acc2[i][jp], a_pk[i], b_pk[jp]);
        }

        if (has_next) WSTORE(buf ^ 1);
        __syncthreads();
        buf ^= 1;
    }
    #undef WLOAD
    #undef WSTORE

    #pragma unroll
    for (int i = 0; i < 4; i++) {
        const int r = row0 + ty * 4 + i;
        #pragma unroll
        for (int jp = 0; jp < 2; jp++) {
            float2 yv = funpack(acc2[i][jp]);
            #pragma unroll
            for (int l = 0; l < 2; l++) {
                const int col = bx * WBN + tx * 4 + jp * 2 + l;
                const size_t idx = (size_t)r * DIM + col;
                C[idx] = addv[idx] + ((l == 0) ? yv.x : yv.y);
            }
        }
    }
}

// ---------------------------------------------------------------------------
// gate = (c1/10) * ((c3p - c3n)/10)
// ---------------------------------------------------------------------------
__global__ void gate_kernel(const float* __restrict__ c1,
                            const float* __restrict__ c3p,
                            const float* __restrict__ c3n,
                            float* __restrict__ g)
{
    const int i = blockIdx.x * blockDim.x + threadIdx.x;
    if (i < NTOK * HIDDEN)
        g[i] = (c1[i] / 10.0f) * ((c3p[i] - c3n[i]) / 10.0f);
}

// ---------------------------------------------------------------------------
// Spike attention (bit-frozen)
// ---------------------------------------------------------------------------
__global__ void attn_kernel(const unsigned* __restrict__ qm,
                            const unsigned* __restrict__ km,
                            const unsigned* __restrict__ vm,
                            float* __restrict__ xat)
{
    __shared__ unsigned sq[128 * 33];
    __shared__ unsigned sk[128 * 9];
    __shared__ unsigned sv[8 * 128];
    __shared__ int      S[NHEAD * 8];

    const int n   = blockIdx.x;
    const int tid = threadIdx.x;

    for (int idx = tid; idx < NHEAD * HDIM; idx += 128) {
        const int i = idx >> 7, d = idx & 127;
        sq[d * 33 + i] = qm[(size_t)n * DIM + idx] | (qm[(size_t)(n + NTOK) * DIM + idx] << 16);
    }
    for (int idx = tid; idx < 8 * HDIM; idx += 128) {
        const int j = idx >> 7, d = idx & 127;
        sk[d * 9 + j] = km[(size_t)n * KVDIM + idx] | (km[(size_t)(n + NTOK) * KVDIM + idx] << 16);
        sv[idx]       = vm[(size_t)n * KVDIM + idx] | (vm[(size_t)(n + NTOK) * KVDIM + idx] << 16);
    }
    __syncthreads();

    for (int t = 0; t < TSTEPS; t++) {
        #pragma unroll
        for (int e0 = 0; e0 < 2; e0++) {
            const int e = tid + e0 * 128;
            const int i = e >> 3, j = e & 7;
            int s = 0;
            for (int d2 = 0; d2 < HDIM; d2++) {
                const unsigned q = sq[d2 * 33 + i];
                const unsigned k = sk[d2 * 9 + j];
                const int qv = (int)((q >> t) & 1u) - (int)((q >> (t + 16)) & 1u);
                const int kv = (int)((k >> t) & 1u) - (int)((k >> (t + 16)) & 1u);
                s += qv * kv;
            }
            S[e] = s;
        }
        __syncthreads();

        {
            const int d2 = tid;
            int vv[8];
            #pragma unroll
            for (int j = 0; j < 8; j++) {
                const unsigned v = sv[j * 128 + d2];
                vv[j] = (int)((v >> t) & 1u) - (int)((v >> (t + 16)) & 1u);
            }
            float* orow = xat + ((size_t)t * NTOK + n) * DIM + (size_t)d2 * NHEAD;
            #pragma unroll
            for (int i = 0; i < NHEAD; i++) {
                int s = 0;
                #pragma unroll
                for (int j = 0; j < 8; j++) s += S[i * 8 + j] * vv[j];
                orow[i] = (float)s * 0.5f;
            }
        }
        __syncthreads();
    }
}

// ---------------------------------------------------------------------------
// h = x + mean_t(y_t) (bit-frozen)
// ---------------------------------------------------------------------------
__global__ void wo_mean_kernel(const float* __restrict__ yt,
                               const float* __restrict__ x,
                               float* __restrict__ h)
{
    const int idx = blockIdx.x * blockDim.x + threadIdx.x;
    if (idx >= NTOK * DIM) return;
    float s = 0.f;
    #pragma unroll
    for (int t = 0; t < TSTEPS; t++)
        s += yt[(size_t)t * NTOK * DIM + idx];
    h[idx] = x[idx] + s / 10.0f;
}

// ---------------------------------------------------------------------------
// Launch
// ---------------------------------------------------------------------------
extern "C" void kernel_launch(void* const* d_in, const int* in_sizes, int n_in,
                              void* d_out, int out_size)
{
    const float* x           = (const float*)d_in[0];
    const float* attn_norm_w = (const float*)d_in[2];
    const float* ffn_norm_w  = (const float*)d_in[3];
    const float* wq          = (const float*)d_in[4];
    const float* wk          = (const float*)d_in[5];
    const float* wv          = (const float*)d_in[6];
    const float* wo          = (const float*)d_in[7];
    const float* w1          = (const float*)d_in[8];
    const float* w2          = (const float*)d_in[9];
    const float* w3          = (const float*)d_in[10];
    float* out = (float*)d_out;

    float *xs, *hs, *xat, *yt, *h, *c3, *c1, *gate;
    unsigned *qm, *km, *vm;
    cudaGetSymbolAddress((void**)&xs,   g_xs);
    cudaGetSymbolAddress((void**)&hs,   g_hs);
    cudaGetSymbolAddress((void**)&qm,   g_qm);
    cudaGetSymbolAddress((void**)&km,   g_km);
    cudaGetSymbolAddress((void**)&vm,   g_vm);
    cudaGetSymbolAddress((void**)&xat,  g_xat);
    cudaGetSymbolAddress((void**)&yt,   g_yt);
    cudaGetSymbolAddress((void**)&h,    g_h);
    cudaGetSymbolAddress((void**)&c3,   g_c3);
    cudaGetSymbolAddress((void**)&c1,   g_c1);
    cudaGetSymbolAddress((void**)&gate, g_gate);

    // 1) attn rmsnorm + stacked relu
    rmsnorm_relu_kernel<<<NTOK, 1024>>>(x, attn_norm_w, xs);

    // 2) fused QKV spike-mask projections (split-K=4, FFMA2)
    gemm_qkv_kernel<<<dim3(96, 4), 256>>>(xs, wq, wk, wv, qm, km, vm, DIM);

    // 3) exact spike attention -> per-timestep planes
    attn_kernel<<<NTOK, 128>>>(qm, km, vm, xat);

    // 4) per-t wo GEMM: yt = xat @ wo^T  (M=2560, FFMA2, conflict-free frags)
    gemm2_kernel<2><<<dim3(32, 20), 256>>>(xat, wo, nullptr, yt, nullptr, DIM);

    // 5) h = x + mean_t(y_t)
    wo_mean_kernel<<<(NTOK * DIM + 255) / 256, 256>>>(yt, x, h);

    // 6) ffn rmsnorm + stacked relu
    rmsnorm_relu_kernel<<<NTOK, 1024>>>(h, ffn_norm_w, hs);

    // 7) fused FFN spike-count projections: w3 (M=512) + w1 (M=256)
    gemm2_kernel<1><<<dim3(112, 6), 256>>>(hs, w3, w1, c3, c1, DIM);

    // 8) gate (elementwise)
    gate_kernel<<<(NTOK * HIDDEN + 255) / 256, 256>>>(c1, c3, c3 + (size_t)NTOK * HIDDEN, gate);

    // 9) out = h + gate @ w2^T
    gemm_w2_kernel<<<dim3(64, 4), 256>>>(gate, w2, out, h, HIDDEN);
}

// round 12
// speedup vs baseline: 1.9996x; 1.0535x over previous
#include <cuda_runtime.h>
#include <cstdint>

// ---------------------------------------------------------------------------
// Problem constants
// ---------------------------------------------------------------------------
#define NTOK   256
#define DIM    4096
#define HIDDEN 14336
#define KVDIM  1024
#define NHEAD  32
#define HDIM   128
#define TSTEPS 10

typedef unsigned long long u64;

// ---------------------------------------------------------------------------
// Packed f32x2 helpers (sm_103a FFMA2 path — only reachable via PTX).
// ---------------------------------------------------------------------------
__device__ __forceinline__ u64 fdup(float a) {
    u64 r; asm("mov.b64 %0, {%1, %1};" : "=l"(r) : "f"(a)); return r;
}
__device__ __forceinline__ void ffma2(u64& d, u64 a, u64 b) {
    asm("fma.rn.f32x2 %0, %1, %2, %0;" : "+l"(d) : "l"(a), "l"(b));
}
__device__ __forceinline__ void fadd2(u64& d, u64 a) {
    asm("add.rn.f32x2 %0, %0, %1;" : "+l"(d) : "l"(a));
}
__device__ __forceinline__ float2 funpack(u64 v) {
    float lo, hi; asm("mov.b64 {%0, %1}, %2;" : "=f"(lo), "=f"(hi) : "l"(v));
    return make_float2(lo, hi);
}

// ---------------------------------------------------------------------------
// Scratch (device globals)
// ---------------------------------------------------------------------------
__device__ float    g_xs [2 * NTOK * DIM];
__device__ float    g_hs [2 * NTOK * DIM];
__device__ unsigned g_qm [2 * NTOK * DIM];
__device__ unsigned g_km [2 * NTOK * KVDIM];
__device__ unsigned g_vm [2 * NTOK * KVDIM];
__device__ float    g_xat[TSTEPS * NTOK * DIM];
__device__ float    g_yt [TSTEPS * NTOK * DIM];
__device__ float    g_h  [NTOK * DIM];
__device__ float    g_c3 [2 * NTOK * HIDDEN];
__device__ float    g_c1 [NTOK * HIDDEN];
__device__ float    g_gate[NTOK * HIDDEN];

// ---------------------------------------------------------------------------
// RMSNorm + stacked relu (bit-frozen)
// ---------------------------------------------------------------------------
__global__ __launch_bounds__(1024)
void rmsnorm_relu_kernel(const float* __restrict__ x,
                         const float* __restrict__ w,
                         float* __restrict__ out)
{
    const int n = blockIdx.x;
    const int t = threadIdx.x;
    const float* xr = x + (size_t)n * DIM;

    float acc = 0.f;
    #pragma unroll
    for (int i = 0; i < 2; i++) {
        float2 v = *(const float2*)(xr + 2 * t + i * 2048);
        acc += v.x * v.x;
        acc += v.y * v.y;
    }
    #pragma unroll
    for (int o = 16; o > 0; o >>= 1)
        acc += __shfl_down_sync(0xffffffffu, acc, o);

    __shared__ float sw[32];
    __shared__ float sres;
    const int lane = t & 31, wid = t >> 5;
    if (lane == 0) sw[wid] = acc;
    __syncthreads();
    if (wid == 0) {
        float v = sw[lane];
        #pragma unroll
        for (int o = 16; o > 0; o >>= 1)
            v += __shfl_down_sync(0xffffffffu, v, o);
        if (lane == 0) sres = v;
    }
    __syncthreads();

    const float rs = rsqrtf(sres * (1.0f / 4096.0f) + 1e-5f);
    #pragma unroll
    for (int i = 0; i < 4; i++) {
        const int c = t + i * 1024;
        float v = xr[c] * rs * w[c];
        out[(size_t)n * DIM + c]          = fmaxf(v, 0.f);
        out[(size_t)(n + NTOK) * DIM + c] = fmaxf(-v, 0.f);
    }
}

// ---------------------------------------------------------------------------
// QKV GEMM: split-K=4 emulation, FFMA2 (bit-frozen numerics).
// ---------------------------------------------------------------------------
#define QBM 128
#define QBN 64
#define QBK 16
#define SPLITK_CHUNK 1024

__global__ __launch_bounds__(256, 2)
void gemm_qkv_kernel(const float* __restrict__ A,
                     const float* __restrict__ B0,
                     const float* __restrict__ B1,
                     const float* __restrict__ B2,
                     unsigned* __restrict__ C0, unsigned* __restrict__ C1,
                     unsigned* __restrict__ C2, int K)
{
    __shared__ float As[2][QBK][QBM];
    __shared__ float Bs[2][QBK][QBN];

    const int bx = blockIdx.x, by = blockIdx.y;
    const float* B; unsigned* C; int N, bxl;
    const int row0 = by * QBM;
    if (bx < 64)      { B = B0; C = C0; N = DIM;   bxl = bx; }
    else if (bx < 80) { B = B1; C = C1; N = KVDIM; bxl = bx - 64; }
    else              { B = B2; C = C2; N = KVDIM; bxl = bx - 80; }

    const int tid = threadIdx.x;
    const int tx = tid & 15;
    const int ty = tid >> 4;

    const int lrowA = tid >> 1;
    const int lcolA = (tid & 1) * 8;
    const int lrowB = tid >> 2;
    const int lcolB = (tid & 3) * 4;

    const float* Aptr = A + (size_t)(row0 + lrowA) * K + lcolA;
    const float* Bptr = B + (size_t)(bxl * QBN + lrowB) * K + lcolB;

    u64 acc2[8][2], tot2[8][2];
    #pragma unroll
    for (int i = 0; i < 8; i++)
        #pragma unroll
        for (int j = 0; j < 2; j++) { acc2[i][j] = 0ULL; tot2[i][j] = 0ULL; }

    float4 a0s, a1s, b0s;
    #define QLOAD()                                                            \
        do {                                                                   \
            a0s = *(const float4*)Aptr;                                        \
            a1s = *(const float4*)(Aptr + 4);                                  \
            b0s = *(const float4*)Bptr;                                        \
            Aptr += QBK; Bptr += QBK;                                          \
        } while (0)
    #define QSTORE(BUF)                                                        \
        do {                                                                   \
            As[BUF][lcolA + 0][lrowA] = a0s.x; As[BUF][lcolA + 1][lrowA] = a0s.y; \
            As[BUF][lcolA + 2][lrowA] = a0s.z; As[BUF][lcolA + 3][lrowA] = a0s.w; \
            As[BUF][lcolA + 4][lrowA] = a1s.x; As[BUF][lcolA + 5][lrowA] = a1s.y; \
            As[BUF][lcolA + 6][lrowA] = a1s.z; As[BUF][lcolA + 7][lrowA] = a1s.w; \
            Bs[BUF][lcolB + 0][lrowB] = b0s.x; Bs[BUF][lcolB + 1][lrowB] = b0s.y; \
            Bs[BUF][lcolB + 2][lrowB] = b0s.z; Bs[BUF][lcolB + 3][lrowB] = b0s.w; \
        } while (0)

    QLOAD(); QSTORE(0);
    __syncthreads();

    int buf = 0;
    for (int k0 = 0; k0 < K; k0 += QBK) {
        const bool has_next = (k0 + QBK < K);
        if (has_next) QLOAD();

        #pragma unroll
        for (int kk = 0; kk < QBK; kk++) {
            float4 a0 = *(const float4*)&As[buf][kk][ty * 8];
            float4 a1 = *(const float4*)&As[buf][kk][ty * 8 + 4];
            ulonglong2 bp = *(const ulonglong2*)&Bs[buf][kk][tx * 4];
            u64 b_pk[2] = { bp.x, bp.y };
            u64 a_pk[8] = { fdup(a0.x), fdup(a0.y), fdup(a0.z), fdup(a0.w),
                            fdup(a1.x), fdup(a1.y), fdup(a1.z), fdup(a1.w) };
            #pragma unroll
            for (int i = 0; i < 8; i++)
                #pragma unroll
                for (int jp = 0; jp < 2; jp++)
                    ffma2(acc2[i][jp], a_pk[i], b_pk[jp]);
        }

        if (((k0 + QBK) & (SPLITK_CHUNK - 1)) == 0) {
            #pragma unroll
            for (int i = 0; i < 8; i++)
                #pragma unroll
                for (int jp = 0; jp < 2; jp++) {
                    fadd2(tot2[i][jp], acc2[i][jp]);
                    acc2[i][jp] = 0ULL;
                }
        }

        if (has_next) QSTORE(buf ^ 1);
        __syncthreads();
        buf ^= 1;
    }
    #undef QLOAD
    #undef QSTORE

    #pragma unroll
    for (int i = 0; i < 8; i++) {
        const int r = row0 + ty * 8 + i;
        #pragma unroll
        for (int jp = 0; jp < 2; jp++) {
            float2 yv = funpack(tot2[i][jp]);
            #pragma unroll
            for (int l = 0; l < 2; l++) {
                const int col = bxl * QBN + tx * 4 + jp * 2 + l;
                float y = (l == 0) ? yv.x : yv.y;
                unsigned m = 0; float vm = 0.f;
                #pragma unroll
                for (int t = 0; t < TSTEPS; t++) {
                    vm += y;
                    if (vm - 1.0f >= 0.f) { m |= (1u << t); vm = 0.f; }
                }
                C[(size_t)r * N + col] = m;
            }
        }
    }
}

// ---------------------------------------------------------------------------
// Big GEMM (NT), 128x128 tile, 8x8/thread, BK=16, double-buffered smem,
// FFMA2, split fragments (conflict-free), and SOFTWARE-PIPELINED fragment
// registers: kk+1's LDS issued before kk's compute (loads reordered only —
// per-element FMA order unchanged -> bit-exact).
// ---------------------------------------------------------------------------
#define BM2 128
#define BN2 128
#define BK2 16

template<int MODE>
__global__ __launch_bounds__(256, 2)
void gemm2_kernel(const float* __restrict__ A,
                  const float* __restrict__ B0,
                  const float* __restrict__ B1,
                  void* __restrict__ C0, void* __restrict__ C1, int K)
{
    __shared__ float As[2][BK2][BM2];
    __shared__ float Bs[2][BK2][BN2];

    const int bx = blockIdx.x, by = blockIdx.y;
    const float* B; void* C; int N, row0;
    if (MODE == 1) {
        N = HIDDEN;
        if (by < 4) { B = B0; C = C0; row0 = by * BM2; }
        else        { B = B1; C = C1; row0 = (by - 4) * BM2; }
    } else {
        N = DIM; B = B0; C = C0; row0 = by * BM2;
    }

    const int tid = threadIdx.x;
    const int tx = tid & 15;
    const int ty = tid >> 4;
    const int lrow = tid >> 1;
    const int lcol = (tid & 1) * 8;

    const float* Aptr = A + (size_t)(row0 + lrow) * K + lcol;
    const float* Bptr = B + (size_t)(bx * BN2 + lrow) * K + lcol;

    u64 acc2[8][4];
    #pragma unroll
    for (int i = 0; i < 8; i++)
        #pragma unroll
        for (int jp = 0; jp < 4; jp++) acc2[i][jp] = 0ULL;

    float4 a0s, a1s, b0s, b1s;
    #define GLOAD()                                                            \
        do {                                                                   \
            a0s = *(const float4*)Aptr;                                        \
            a1s = *(const float4*)(Aptr + 4);                                  \
            b0s = *(const float4*)Bptr;                                        \
            b1s = *(const float4*)(Bptr + 4);                                  \
            Aptr += BK2; Bptr += BK2;                                          \
        } while (0)
    #define GSTORE(BUF)                                                        \
        do {                                                                   \
            As[BUF][lcol + 0][lrow] = a0s.x; As[BUF][lcol + 1][lrow] = a0s.y;  \
            As[BUF][lcol + 2][lrow] = a0s.z; As[BUF][lcol + 3][lrow] = a0s.w;  \
            As[BUF][lcol + 4][lrow] = a1s.x; As[BUF][lcol + 5][lrow] = a1s.y;  \
            As[BUF][lcol + 6][lrow] = a1s.z; As[BUF][lcol + 7][lrow] = a1s.w;  \
            Bs[BUF][lcol + 0][lrow] = b0s.x; Bs[BUF][lcol + 1][lrow] = b0s.y;  \
            Bs[BUF][lcol + 2][lrow] = b0s.z; Bs[BUF][lcol + 3][lrow] = b0s.w;  \
            Bs[BUF][lcol + 4][lrow] = b1s.x; Bs[BUF][lcol + 5][lrow] = b1s.y;  \
            Bs[BUF][lcol + 6][lrow] = b1s.z; Bs[BUF][lcol + 7][lrow] = b1s.w;  \
        } while (0)

    // fragment registers (double-buffered over kk)
    float4     fa0[2], fa1[2];
    ulonglong2 fb0[2], fb1[2];
    #define FRAG_LOAD(P, BUF, KK)                                              \
        do {                                                                   \
            fa0[P] = *(const float4*)&As[BUF][KK][ty * 4];                     \
            fa1[P] = *(const float4*)&As[BUF][KK][64 + ty * 4];                \
            fb0[P] = *(const ulonglong2*)&Bs[BUF][KK][tx * 4];                 \
            fb1[P] = *(const ulonglong2*)&Bs[BUF][KK][64 + tx * 4];            \
        } while (0)

    GLOAD(); GSTORE(0);
    __syncthreads();

    int buf = 0;
    for (int k0 = 0; k0 < K; k0 += BK2) {
        const bool has_next = (k0 + BK2 < K);
        if (has_next) GLOAD();

        FRAG_LOAD(0, buf, 0);
        #pragma unroll
        for (int kk = 0; kk < BK2; kk++) {
            const int p = kk & 1;
            if (kk + 1 < BK2) FRAG_LOAD(p ^ 1, buf, kk + 1);

            u64 b_pk[4] = { fb0[p].x, fb0[p].y, fb1[p].x, fb1[p].y };
            u64 a_pk[8] = { fdup(fa0[p].x), fdup(fa0[p].y),
                            fdup(fa0[p].z), fdup(fa0[p].w),
                            fdup(fa1[p].x), fdup(fa1[p].y),
                            fdup(fa1[p].z), fdup(fa1[p].w) };
            #pragma unroll
            for (int i = 0; i < 8; i++)
                #pragma unroll
                for (int jp = 0; jp < 4; jp++)
                    ffma2(acc2[i][jp], a_pk[i], b_pk[jp]);
        }

        if (has_next) GSTORE(buf ^ 1);
        __syncthreads();
        buf ^= 1;
    }
    #undef GLOAD
    #undef GSTORE
    #undef FRAG_LOAD

    #pragma unroll
    for (int i = 0; i < 8; i++) {
        const int r = row0 + ((i < 4) ? (ty * 4 + i) : (64 + ty * 4 + (i - 4)));
        #pragma unroll
        for (int jp = 0; jp < 4; jp++) {
            const int colbase = bx * BN2 +
                ((jp < 2) ? (tx * 4 + jp * 2) : (64 + tx * 4 + (jp - 2) * 2));
            float2 yv = funpack(acc2[i][jp]);
            #pragma unroll
            for (int l = 0; l < 2; l++) {
                const size_t idx = (size_t)r * N + colbase + l;
                float y = (l == 0) ? yv.x : yv.y;
                if (MODE == 1) {
                    int cnt = 0; float vm = 0.f;
                    #pragma unroll
                    for (int t = 0; t < TSTEPS; t++) {
                        vm += y;
                        if (vm - 1.0f >= 0.f) { cnt++; vm = 0.f; }
                    }
                    ((float*)C)[idx] = (float)cnt;
                } else {
                    ((float*)C)[idx] = y;
                }
            }
        }
    }
}

// ---------------------------------------------------------------------------
// w2 GEMM: 64x64 tile (256 CTAs), BK=32, 4x4/thread, FFMA2.
// ---------------------------------------------------------------------------
#define WBM 64
#define WBN 64
#define WBK 32

__global__ __launch_bounds__(256)
void gemm_w2_kernel(const float* __restrict__ A,
                    const float* __restrict__ B,
                    float* __restrict__ C,
                    const float* __restrict__ addv, int K)
{
    __shared__ float As[2][WBK][WBM];
    __shared__ float Bs[2][WBK][WBN];

    const int bx = blockIdx.x, by = blockIdx.y;
    const int row0 = by * WBM;
    const int tid = threadIdx.x;
    const int tx = tid & 15;
    const int ty = tid >> 4;
    const int lrow = tid >> 2;
    const int lcol = (tid & 3) * 8;

    const float* Aptr = A + (size_t)(row0 + lrow) * K + lcol;
    const float* Bptr = B + (size_t)(bx * WBN + lrow) * K + lcol;

    u64 acc2[4][2];
    #pragma unroll
    for (int i = 0; i < 4; i++)
        #pragma unroll
        for (int jp = 0; jp < 2; jp++) acc2[i][jp] = 0ULL;

    float4 a0s, a1s, b0s, b1s;
    #define WLOAD()                                                            \
        do {                                                                   \
            a0s = *(const float4*)Aptr;                                        \
            a1s = *(const float4*)(Aptr + 4);                                  \
            b0s = *(const float4*)Bptr;                                        \
            b1s = *(const float4*)(Bptr + 4);                                  \
            Aptr += WBK; Bptr += WBK;                                          \
        } while (0)
    #define WSTORE(BUF)                                                        \
        do {                                                                   \
            As[BUF][lcol + 0][lrow] = a0s.x; As[BUF][lcol + 1][lrow] = a0s.y;  \
            As[BUF][lcol + 2][lrow] = a0s.z; As[BUF][lcol + 3][lrow] = a0s.w;  \
            As[BUF][lcol + 4][lrow] = a1s.x; As[BUF][lcol + 5][lrow] = a1s.y;  \
            As[BUF][lcol + 6][lrow] = a1s.z; As[BUF][lcol + 7][lrow] = a1s.w;  \
            Bs[BUF][lcol + 0][lrow] = b0s.x; Bs[BUF][lcol + 1][lrow] = b0s.y;  \
            Bs[BUF][lcol + 2][lrow] = b0s.z; Bs[BUF][lcol + 3][lrow] = b0s.w;  \
            Bs[BUF][lcol + 4][lrow] = b1s.x; Bs[BUF][lcol + 5][lrow] = b1s.y;  \
            Bs[BUF][lcol + 6][lrow] = b1s.z; Bs[BUF][lcol + 7][lrow] = b1s.w;  \
        } while (0)

    WLOAD(); WSTORE(0);
    __syncthreads();

    int buf = 0;
    for (int k0 = 0; k0 < K; k0 += WBK) {
        const bool has_next = (k0 + WBK < K);
        if (has_next) WLOAD();

        #pragma unroll
        for (int kk = 0; kk < WBK; kk++) {
            float4 a0 = *(const float4*)&As[buf][kk][ty * 4];
            ulonglong2 bp = *(const ulonglong2*)&Bs[buf][kk][tx * 4];
            u64 b_pk[2] = { bp.x, bp.y };
            u64 a_pk[4] = { fdup(a0.x), fdup(a0.y), fdup(a0.z), fdup(a0.w) };
            #pragma unroll
            for (int i = 0; i < 4; i++)
                #pragma unroll
                for (int jp = 0; jp < 2; jp++)
                    ffma2(acc2[i][jp], a_pk[i], b_pk[jp]);
        }

        if (has_next) WSTORE(buf ^ 1);
        __syncthreads();
        buf ^= 1;
    }
    #undef WLOAD
    #undef WSTORE

    #pragma unroll
    for (int i = 0; i < 4; i++) {
        const int r = row0 + ty * 4 + i;
        #pragma unroll
        for (int jp = 0; jp < 2; jp++) {
            float2 yv = funpack(acc2[i][jp]);
            #pragma unroll
            for (int l = 0; l < 2; l++) {
                const int col = bx * WBN + tx * 4 + jp * 2 + l;
                const size_t idx = (size_t)r * DIM + col;
                C[idx] = addv[idx] + ((l == 0) ? yv.x : yv.y);
            }
        }
    }
}

// ---------------------------------------------------------------------------
// gate = (c1/10) * ((c3p - c3n)/10)
// ---------------------------------------------------------------------------
__global__ void gate_kernel(const float* __restrict__ c1,
                            const float* __restrict__ c3p,
                            const float* __restrict__ c3n,
                            float* __restrict__ g)
{
    const int i = blockIdx.x * blockDim.x + threadIdx.x;
    if (i < NTOK * HIDDEN)
        g[i] = (c1[i] / 10.0f) * ((c3p[i] - c3n[i]) / 10.0f);
}

// ---------------------------------------------------------------------------
// Spike attention (bit-frozen)
// ---------------------------------------------------------------------------
__global__ void attn_kernel(const unsigned* __restrict__ qm,
                            const unsigned* __restrict__ km,
                            const unsigned* __restrict__ vm,
                            float* __restrict__ xat)
{
    __shared__ unsigned sq[128 * 33];
    __shared__ unsigned sk[128 * 9];
    __shared__ unsigned sv[8 * 128];
    __shared__ int      S[NHEAD * 8];

    const int n   = blockIdx.x;
    const int tid = threadIdx.x;

    for (int idx = tid; idx < NHEAD * HDIM; idx += 128) {
        const int i = idx >> 7, d = idx & 127;
        sq[d * 33 + i] = qm[(size_t)n * DIM + idx] | (qm[(size_t)(n + NTOK) * DIM + idx] << 16);
    }
    for (int idx = tid; idx < 8 * HDIM; idx += 128) {
        const int j = idx >> 7, d = idx & 127;
        sk[d * 9 + j] = km[(size_t)n * KVDIM + idx] | (km[(size_t)(n + NTOK) * KVDIM + idx] << 16);
        sv[idx]       = vm[(size_t)n * KVDIM + idx] | (vm[(size_t)(n + NTOK) * KVDIM + idx] << 16);
    }
    __syncthreads();

    for (int t = 0; t < TSTEPS; t++) {
        #pragma unroll
        for (int e0 = 0; e0 < 2; e0++) {
            const int e = tid + e0 * 128;
            const int i = e >> 3, j = e & 7;
            int s = 0;
            for (int d2 = 0; d2 < HDIM; d2++) {
                const unsigned q = sq[d2 * 33 + i];
                const unsigned k = sk[d2 * 9 + j];
                const int qv = (int)((q >> t) & 1u) - (int)((q >> (t + 16)) & 1u);
                const int kv = (int)((k >> t) & 1u) - (int)((k >> (t + 16)) & 1u);
                s += qv * kv;
            }
            S[e] = s;
        }
        __syncthreads();

        {
            const int d2 = tid;
            int vv[8];
            #pragma unroll
            for (int j = 0; j < 8; j++) {
                const unsigned v = sv[j * 128 + d2];
                vv[j] = (int)((v >> t) & 1u) - (int)((v >> (t + 16)) & 1u);
            }
            float* orow = xat + ((size_t)t * NTOK + n) * DIM + (size_t)d2 * NHEAD;
            #pragma unroll
            for (int i = 0; i < NHEAD; i++) {
                int s = 0;
                #pragma unroll
                for (int j = 0; j < 8; j++) s += S[i * 8 + j] * vv[j];
                orow[i] = (float)s * 0.5f;
            }
        }
        __syncthreads();
    }
}

// ---------------------------------------------------------------------------
// h = x + mean_t(y_t) (bit-frozen)
// ---------------------------------------------------------------------------
__global__ void wo_mean_kernel(const float* __restrict__ yt,
                               const float* __restrict__ x,
                               float* __restrict__ h)
{
    const int idx = blockIdx.x * blockDim.x + threadIdx.x;
    if (idx >= NTOK * DIM) return;
    float s = 0.f;
    #pragma unroll
    for (int t = 0; t < TSTEPS; t++)
        s += yt[(size_t)t * NTOK * DIM + idx];
    h[idx] = x[idx] + s / 10.0f;
}

// ---------------------------------------------------------------------------
// Launch
// ---------------------------------------------------------------------------
extern "C" void kernel_launch(void* const* d_in, const int* in_sizes, int n_in,
                              void* d_out, int out_size)
{
    const float* x           = (const float*)d_in[0];
    const float* attn_norm_w = (const float*)d_in[2];
    const float* ffn_norm_w  = (const float*)d_in[3];
    const float* wq          = (const float*)d_in[4];
    const float* wk          = (const float*)d_in[5];
    const float* wv          = (const float*)d_in[6];
    const float* wo          = (const float*)d_in[7];
    const float* w1          = (const float*)d_in[8];
    const float* w2          = (const float*)d_in[9];
    const float* w3          = (const float*)d_in[10];
    float* out = (float*)d_out;

    float *xs, *hs, *xat, *yt, *h, *c3, *c1, *gate;
    unsigned *qm, *km, *vm;
    cudaGetSymbolAddress((void**)&xs,   g_xs);
    cudaGetSymbolAddress((void**)&hs,   g_hs);
    cudaGetSymbolAddress((void**)&qm,   g_qm);
    cudaGetSymbolAddress((void**)&km,   g_km);
    cudaGetSymbolAddress((void**)&vm,   g_vm);
    cudaGetSymbolAddress((void**)&xat,  g_xat);
    cudaGetSymbolAddress((void**)&yt,   g_yt);
    cudaGetSymbolAddress((void**)&h,    g_h);
    cudaGetSymbolAddress((void**)&c3,   g_c3);
    cudaGetSymbolAddress((void**)&c1,   g_c1);
    cudaGetSymbolAddress((void**)&gate, g_gate);

    // 1) attn rmsnorm + stacked relu
    rmsnorm_relu_kernel<<<NTOK, 1024>>>(x, attn_norm_w, xs);

    // 2) fused QKV spike-mask projections (split-K=4, FFMA2)
    gemm_qkv_kernel<<<dim3(96, 4), 256>>>(xs, wq, wk, wv, qm, km, vm, DIM);

    // 3) exact spike attention -> per-timestep planes
    attn_kernel<<<NTOK, 128>>>(qm, km, vm, xat);

    // 4) per-t wo GEMM: yt = xat @ wo^T  (M=2560, software-pipelined frags)
    gemm2_kernel<2><<<dim3(32, 20), 256>>>(xat, wo, nullptr, yt, nullptr, DIM);

    // 5) h = x + mean_t(y_t)
    wo_mean_kernel<<<(NTOK * DIM + 255) / 256, 256>>>(yt, x, h);

    // 6) ffn rmsnorm + stacked relu
    rmsnorm_relu_kernel<<<NTOK, 1024>>>(h, ffn_norm_w, hs);

    // 7) fused FFN spike-count projections: w3 (M=512) + w1 (M=256)
    gemm2_kernel<1><<<dim3(112, 6), 256>>>(hs, w3, w1, c3, c1, DIM);

    // 8) gate (elementwise)
    gate_kernel<<<(NTOK * HIDDEN + 255) / 256, 256>>>(c1, c3, c3 + (size_t)NTOK * HIDDEN, gate);

    // 9) out = h + gate @ w2^T
    gemm_w2_kernel<<<dim3(64, 4), 256>>>(gate, w2, out, h, HIDDEN);
}